// round 4
// baseline (speedup 1.0000x reference)
#include <cuda_runtime.h>

// ---------------------------------------------------------------------------
// Problem constants (fixed by the reference setup)
// ---------------------------------------------------------------------------
#define EMBED    1024
#define HEADS    16
#define HEAD_DIM 64
#define FFN_DIM  4096
#define BSZ      2
#define SUM_LEN  16
#define REG_LEN  2048
#define TOTAL    (SUM_LEN + REG_LEN)   // 2064
#define NCHUNK   16
#define NTOK     (BSZ * TOTAL)         // 4128
#define MAXKEYS  144                   // 15 sum + 128 reg (one chunk)
#define ATTN_SMEM (MAXKEYS * HEAD_DIM * 2 * 4)  // K + V tiles, fp32

// ---------------------------------------------------------------------------
// Static device scratch (no cudaMalloc allowed)
// ---------------------------------------------------------------------------
__device__ float g_h  [(size_t)NTOK * EMBED];
__device__ float g_q  [(size_t)NTOK * EMBED];
__device__ float g_k  [(size_t)NTOK * EMBED];
__device__ float g_v  [(size_t)NTOK * EMBED];
__device__ float g_ctx[(size_t)NTOK * EMBED];
__device__ float g_x1 [(size_t)NTOK * EMBED];
__device__ float g_h2 [(size_t)NTOK * EMBED];
__device__ float g_mid[(size_t)NTOK * FFN_DIM];

// ---------------------------------------------------------------------------
// LayerNorm: one block per row (1024 floats), 256 threads, float4 I/O.
// Selects sum/reg gamma+beta by token position.
// ---------------------------------------------------------------------------
__global__ __launch_bounds__(256) void ln_kernel(
    const float* __restrict__ x,
    const float* __restrict__ gs, const float* __restrict__ bs,
    const float* __restrict__ gr, const float* __restrict__ br,
    float* __restrict__ out)
{
    int row = blockIdx.x;
    int t = row % TOTAL;
    const float* g = (t < SUM_LEN) ? gs : gr;
    const float* b = (t < SUM_LEN) ? bs : br;
    int tid = threadIdx.x;
    int lane = tid & 31, warp = tid >> 5;

    float4 v = ((const float4*)(x + (size_t)row * EMBED))[tid];
    float s = v.x + v.y + v.z + v.w;
    float q = v.x * v.x + v.y * v.y + v.z * v.z + v.w * v.w;

    __shared__ float rs_[8], rq_[8];
#pragma unroll
    for (int o = 16; o; o >>= 1) {
        s += __shfl_xor_sync(0xffffffffu, s, o);
        q += __shfl_xor_sync(0xffffffffu, q, o);
    }
    if (lane == 0) { rs_[warp] = s; rq_[warp] = q; }
    __syncthreads();
    if (tid < 32) {
        s = (lane < 8) ? rs_[lane] : 0.f;
        q = (lane < 8) ? rq_[lane] : 0.f;
#pragma unroll
        for (int o = 4; o; o >>= 1) {
            s += __shfl_xor_sync(0xffffffffu, s, o);
            q += __shfl_xor_sync(0xffffffffu, q, o);
        }
        if (lane == 0) { rs_[0] = s; rq_[0] = q; }
    }
    __syncthreads();

    float mean = rs_[0] * (1.f / EMBED);
    float var  = rq_[0] * (1.f / EMBED) - mean * mean;
    float rinv = rsqrtf(var + 1e-5f);

    float4 gg = ((const float4*)g)[tid];
    float4 bb = ((const float4*)b)[tid];
    float4 o4;
    o4.x = (v.x - mean) * rinv * gg.x + bb.x;
    o4.y = (v.y - mean) * rinv * gg.y + bb.y;
    o4.z = (v.z - mean) * rinv * gg.z + bb.z;
    o4.w = (v.w - mean) * rinv * gg.w + bb.w;
    ((float4*)(out + (size_t)row * EMBED))[tid] = o4;
}

// ---------------------------------------------------------------------------
// SGEMM (NT):  C[M,N] = op( A[M,K] @ B[N,K]^T + bias[N] ) + resid[M,N]
// 128x128 block tile, BK=8, 256 threads, 8x8 microtile per thread.
// N must be a multiple of 128 (1024 / 4096 here); M is guarded.
// ---------------------------------------------------------------------------
template<bool RELU>
__global__ __launch_bounds__(256) void sgemm_nt(
    const float* __restrict__ A, const float* __restrict__ B,
    float* __restrict__ C, int M, int N, int K,
    const float* __restrict__ bias, const float* __restrict__ resid)
{
    __shared__ float As[8][132];
    __shared__ float Bs[8][132];

    int tid = threadIdx.x;
    int loadRow = tid >> 1;          // 0..127
    int loadCol = (tid & 1) << 2;    // 0 or 4
    int aRow = blockIdx.y * 128 + loadRow;
    int bRow = blockIdx.x * 128 + loadRow;
    bool aok = aRow < M;

    const float* Ap = A + (size_t)(aok ? aRow : 0) * K;
    const float* Bp = B + (size_t)bRow * K;

    int tx = tid & 15, ty = tid >> 4;

    float acc[8][8];
#pragma unroll
    for (int i = 0; i < 8; i++)
#pragma unroll
        for (int j = 0; j < 8; j++) acc[i][j] = 0.f;

    for (int k0 = 0; k0 < K; k0 += 8) {
        float4 a4 = aok ? *(const float4*)(Ap + k0 + loadCol)
                        : make_float4(0.f, 0.f, 0.f, 0.f);
        float4 b4 = *(const float4*)(Bp + k0 + loadCol);
        As[loadCol + 0][loadRow] = a4.x;
        As[loadCol + 1][loadRow] = a4.y;
        As[loadCol + 2][loadRow] = a4.z;
        As[loadCol + 3][loadRow] = a4.w;
        Bs[loadCol + 0][loadRow] = b4.x;
        Bs[loadCol + 1][loadRow] = b4.y;
        Bs[loadCol + 2][loadRow] = b4.z;
        Bs[loadCol + 3][loadRow] = b4.w;
        __syncthreads();

#pragma unroll
        for (int kk = 0; kk < 8; kk++) {
            float ar[8], br[8];
            *(float4*)&ar[0] = *(const float4*)&As[kk][ty * 4];
            *(float4*)&ar[4] = *(const float4*)&As[kk][64 + ty * 4];
            *(float4*)&br[0] = *(const float4*)&Bs[kk][tx * 4];
            *(float4*)&br[4] = *(const float4*)&Bs[kk][64 + tx * 4];
#pragma unroll
            for (int i = 0; i < 8; i++)
#pragma unroll
                for (int j = 0; j < 8; j++)
                    acc[i][j] = fmaf(ar[i], br[j], acc[i][j]);
        }
        __syncthreads();
    }

    int n0 = blockIdx.x * 128 + tx * 4;
    float4 bi0 = make_float4(0.f, 0.f, 0.f, 0.f);
    float4 bi1 = bi0;
    if (bias) {
        bi0 = *(const float4*)(bias + n0);
        bi1 = *(const float4*)(bias + n0 + 64);
    }

#pragma unroll
    for (int i = 0; i < 8; i++) {
        int m = blockIdx.y * 128 + ((i < 4) ? (ty * 4 + i) : (64 + ty * 4 + (i - 4)));
        if (m >= M) continue;
        float4 c0, c1;
        c0.x = acc[i][0] + bi0.x; c0.y = acc[i][1] + bi0.y;
        c0.z = acc[i][2] + bi0.z; c0.w = acc[i][3] + bi0.w;
        c1.x = acc[i][4] + bi1.x; c1.y = acc[i][5] + bi1.y;
        c1.z = acc[i][6] + bi1.z; c1.w = acc[i][7] + bi1.w;
        if (RELU) {
            c0.x = fmaxf(c0.x, 0.f); c0.y = fmaxf(c0.y, 0.f);
            c0.z = fmaxf(c0.z, 0.f); c0.w = fmaxf(c0.w, 0.f);
            c1.x = fmaxf(c1.x, 0.f); c1.y = fmaxf(c1.y, 0.f);
            c1.z = fmaxf(c1.z, 0.f); c1.w = fmaxf(c1.w, 0.f);
        }
        if (resid) {
            float4 r0 = *(const float4*)(resid + (size_t)m * N + n0);
            float4 r1 = *(const float4*)(resid + (size_t)m * N + n0 + 64);
            c0.x += r0.x; c0.y += r0.y; c0.z += r0.z; c0.w += r0.w;
            c1.x += r1.x; c1.y += r1.y; c1.z += r1.z; c1.w += r1.w;
        }
        *(float4*)(C + (size_t)m * N + n0) = c0;
        *(float4*)(C + (size_t)m * N + n0 + 64) = c1;
    }
}

// ---------------------------------------------------------------------------
// Attention for REG queries. Grid (NCHUNK, HEADS, BSZ), 128 threads.
// Keys for chunk c: sum tokens [0, c) + reg tokens of chunk c (causal).
// K/V tiles staged in dynamic smem; one thread per query, online softmax.
// ---------------------------------------------------------------------------
__global__ void attn_reg_kernel(
    const float* __restrict__ Q, const float* __restrict__ K,
    const float* __restrict__ V, const int* __restrict__ ranges,
    float* __restrict__ CTX)
{
    extern __shared__ float sm[];
    float* Ks = sm;
    float* Vs = sm + MAXKEYS * HEAD_DIM;

    int c = blockIdx.x, h = blockIdx.y, b = blockIdx.z;
    int start = ranges[(b * NCHUNK + c) * 2];
    int next  = (c + 1 < NCHUNK) ? ranges[(b * NCHUNK + c + 1) * 2] : REG_LEN;
    int width = next - start;       // 128 for this dataset
    int nsum  = c;                  // sum keys strictly before chunk c
    int nk    = nsum + width;

    // cooperative K/V stage (float4 granularity)
    for (int idx = threadIdx.x; idx < nk * 16; idx += 128) {
        int j = idx >> 4, f = idx & 15;
        int tok = (j < nsum) ? j : (SUM_LEN + start + (j - nsum));
        size_t off = ((size_t)b * TOTAL + tok) * EMBED + h * HEAD_DIM;
        ((float4*)Ks)[j * 16 + f] = ((const float4*)(K + off))[f];
        ((float4*)Vs)[j * 16 + f] = ((const float4*)(V + off))[f];
    }
    __syncthreads();

    for (int qi = threadIdx.x; qi < width; qi += 128) {
        int tq = SUM_LEN + start + qi;
        const float4* qp = (const float4*)(Q + ((size_t)b * TOTAL + tq) * EMBED + h * HEAD_DIM);
        float qreg[64];
#pragma unroll
        for (int f = 0; f < 16; f++) {
            float4 t4 = qp[f];
            qreg[4 * f + 0] = t4.x * 0.125f;
            qreg[4 * f + 1] = t4.y * 0.125f;
            qreg[4 * f + 2] = t4.z * 0.125f;
            qreg[4 * f + 3] = t4.w * 0.125f;
        }
        float m = -1e30f, l = 0.f;
        float ctx[64];
#pragma unroll
        for (int d = 0; d < 64; d++) ctx[d] = 0.f;

        int jmax = nsum + qi + 1;   // valid keys: all sum keys + causal reg keys
        for (int j = 0; j < jmax; j++) {
            const float4* kj = (const float4*)(Ks + j * HEAD_DIM);
            float s0 = 0.f, s1 = 0.f, s2 = 0.f, s3 = 0.f;
#pragma unroll
            for (int f = 0; f < 16; f++) {
                float4 kk = kj[f];
                s0 = fmaf(qreg[4 * f + 0], kk.x, s0);
                s1 = fmaf(qreg[4 * f + 1], kk.y, s1);
                s2 = fmaf(qreg[4 * f + 2], kk.z, s2);
                s3 = fmaf(qreg[4 * f + 3], kk.w, s3);
            }
            float sdot = (s0 + s1) + (s2 + s3);
            float mn = fmaxf(m, sdot);
            float alpha = __expf(m - mn);
            float p = __expf(sdot - mn);
            l = l * alpha + p;
            const float4* vj = (const float4*)(Vs + j * HEAD_DIM);
#pragma unroll
            for (int f = 0; f < 16; f++) {
                float4 vv = vj[f];
                ctx[4 * f + 0] = fmaf(p, vv.x, ctx[4 * f + 0] * alpha);
                ctx[4 * f + 1] = fmaf(p, vv.y, ctx[4 * f + 1] * alpha);
                ctx[4 * f + 2] = fmaf(p, vv.z, ctx[4 * f + 2] * alpha);
                ctx[4 * f + 3] = fmaf(p, vv.w, ctx[4 * f + 3] * alpha);
            }
            m = mn;
        }
        float inv = 1.f / l;
        float4* op = (float4*)(CTX + ((size_t)b * TOTAL + tq) * EMBED + h * HEAD_DIM);
#pragma unroll
        for (int f = 0; f < 16; f++)
            op[f] = make_float4(ctx[4 * f + 0] * inv, ctx[4 * f + 1] * inv,
                                ctx[4 * f + 2] * inv, ctx[4 * f + 3] * inv);
    }
}

// ---------------------------------------------------------------------------
// Attention for SUM queries. One warp per (b, h, s); 512 warps total.
// Keys: sum tokens [0, s] (causal) + ALL reg tokens of chunk s.
// ---------------------------------------------------------------------------
__global__ __launch_bounds__(256) void attn_sum_kernel(
    const float* __restrict__ Q, const float* __restrict__ K,
    const float* __restrict__ V, const int* __restrict__ ranges,
    float* __restrict__ CTX)
{
    int gw = (blockIdx.x * blockDim.x + threadIdx.x) >> 5;
    int lane = threadIdx.x & 31;
    if (gw >= BSZ * HEADS * SUM_LEN) return;
    int b = gw / (HEADS * SUM_LEN);
    int rem = gw % (HEADS * SUM_LEN);
    int h = rem / SUM_LEN;
    int s = rem % SUM_LEN;

    int start = ranges[(b * NCHUNK + s) * 2];
    int next  = (s + 1 < NCHUNK) ? ranges[(b * NCHUNK + s + 1) * 2] : REG_LEN;

    size_t bbase = (size_t)b * TOTAL;
    float2 q2 = ((const float2*)(Q + (bbase + s) * EMBED + h * HEAD_DIM))[lane];
    q2.x *= 0.125f; q2.y *= 0.125f;

    float m = -1e30f, l = 0.f, cx = 0.f, cy = 0.f;

#define ATTN_SUM_STEP(tok_expr)                                                        \
    do {                                                                               \
        int tok = (tok_expr);                                                          \
        float2 kk = ((const float2*)(K + (bbase + tok) * EMBED + h * HEAD_DIM))[lane]; \
        float part = q2.x * kk.x + q2.y * kk.y;                                        \
        _Pragma("unroll")                                                              \
        for (int o = 16; o; o >>= 1) part += __shfl_xor_sync(0xffffffffu, part, o);    \
        float mn = fmaxf(m, part);                                                     \
        float alpha = __expf(m - mn);                                                  \
        float p = __expf(part - mn);                                                   \
        l = l * alpha + p;                                                             \
        float2 vv = ((const float2*)(V + (bbase + tok) * EMBED + h * HEAD_DIM))[lane]; \
        cx = fmaf(p, vv.x, cx * alpha);                                                \
        cy = fmaf(p, vv.y, cy * alpha);                                                \
        m = mn;                                                                        \
    } while (0)

    for (int t = 0; t <= s; t++)       ATTN_SUM_STEP(t);                 // ss causal
    for (int t = start; t < next; t++) ATTN_SUM_STEP(SUM_LEN + t);       // sr: own chunk

#undef ATTN_SUM_STEP

    float inv = 1.f / l;
    ((float2*)(CTX + (bbase + s) * EMBED + h * HEAD_DIM))[lane] =
        make_float2(cx * inv, cy * inv);
}

// ---------------------------------------------------------------------------
// Launch sequence (default stream; fully graph-capturable, no allocs)
// ---------------------------------------------------------------------------
extern "C" void kernel_launch(void* const* d_in, const int* in_sizes, int n_in,
                              void* d_out, int out_size)
{
    const float* x      = (const float*)d_in[0];
    const float* w_q    = (const float*)d_in[1];
    const float* w_k    = (const float*)d_in[2];
    const float* w_v    = (const float*)d_in[3];
    const float* w_o    = (const float*)d_in[4];
    const float* ln1_sg = (const float*)d_in[5];
    const float* ln1_sb = (const float*)d_in[6];
    const float* ln1_rg = (const float*)d_in[7];
    const float* ln1_rb = (const float*)d_in[8];
    const float* sfc1w  = (const float*)d_in[9];
    const float* sfc1b  = (const float*)d_in[10];
    const float* sfc2w  = (const float*)d_in[11];
    const float* sfc2b  = (const float*)d_in[12];
    const float* rfc1w  = (const float*)d_in[13];
    const float* rfc1b  = (const float*)d_in[14];
    const float* rfc2w  = (const float*)d_in[15];
    const float* rfc2b  = (const float*)d_in[16];
    const float* ln2_sg = (const float*)d_in[17];
    const float* ln2_sb = (const float*)d_in[18];
    const float* ln2_rg = (const float*)d_in[19];
    const float* ln2_rb = (const float*)d_in[20];
    const int*   ranges = (const int*)d_in[21];
    float* out = (float*)d_out;

    void *ph, *pq, *pk, *pv, *pctx, *px1, *ph2, *pmid;
    cudaGetSymbolAddress(&ph,   g_h);
    cudaGetSymbolAddress(&pq,   g_q);
    cudaGetSymbolAddress(&pk,   g_k);
    cudaGetSymbolAddress(&pv,   g_v);
    cudaGetSymbolAddress(&pctx, g_ctx);
    cudaGetSymbolAddress(&px1,  g_x1);
    cudaGetSymbolAddress(&ph2,  g_h2);
    cudaGetSymbolAddress(&pmid, g_mid);
    float* h   = (float*)ph;
    float* q   = (float*)pq;
    float* k   = (float*)pk;
    float* v   = (float*)pv;
    float* ctx = (float*)pctx;
    float* x1  = (float*)px1;
    float* h2  = (float*)ph2;
    float* mid = (float*)pmid;

    cudaFuncSetAttribute(attn_reg_kernel,
                         cudaFuncAttributeMaxDynamicSharedMemorySize, ATTN_SMEM);

    // 1) LN1
    ln_kernel<<<NTOK, 256>>>(x, ln1_sg, ln1_sb, ln1_rg, ln1_rb, h);

    // 2) QKV projections
    dim3 gP(EMBED / 128, (NTOK + 127) / 128);
    sgemm_nt<false><<<gP, 256>>>(h, w_q, q, NTOK, EMBED, EMBED, nullptr, nullptr);
    sgemm_nt<false><<<gP, 256>>>(h, w_k, k, NTOK, EMBED, EMBED, nullptr, nullptr);
    sgemm_nt<false><<<gP, 256>>>(h, w_v, v, NTOK, EMBED, EMBED, nullptr, nullptr);

    // 3) Sparse masked attention
    attn_reg_kernel<<<dim3(NCHUNK, HEADS, BSZ), 128, ATTN_SMEM>>>(q, k, v, ranges, ctx);
    attn_sum_kernel<<<(BSZ * HEADS * SUM_LEN) / 8, 256>>>(q, k, v, ranges, ctx);

    // 4) Output projection + residual (x1 = x + ctx @ Wo^T)
    sgemm_nt<false><<<gP, 256>>>(ctx, w_o, x1, NTOK, EMBED, EMBED, nullptr, x);

    // 5) LN2
    ln_kernel<<<NTOK, 256>>>(x1, ln2_sg, ln2_sb, ln2_rg, ln2_rb, h2);

    // 6) FFN: separate weights for sum rows (16) and reg rows (2048), per batch
    for (int b = 0; b < BSZ; b++) {
        // sum segment
        {
            int r0 = b * TOTAL, m = SUM_LEN;
            dim3 g1(FFN_DIM / 128, (m + 127) / 128);
            sgemm_nt<true><<<g1, 256>>>(h2 + (size_t)r0 * EMBED, sfc1w,
                                        mid + (size_t)r0 * FFN_DIM,
                                        m, FFN_DIM, EMBED, sfc1b, nullptr);
            dim3 g2(EMBED / 128, (m + 127) / 128);
            sgemm_nt<false><<<g2, 256>>>(mid + (size_t)r0 * FFN_DIM, sfc2w,
                                         out + (size_t)r0 * EMBED,
                                         m, EMBED, FFN_DIM, sfc2b,
                                         x1 + (size_t)r0 * EMBED);
        }
        // reg segment
        {
            int r0 = b * TOTAL + SUM_LEN, m = REG_LEN;
            dim3 g1(FFN_DIM / 128, (m + 127) / 128);
            sgemm_nt<true><<<g1, 256>>>(h2 + (size_t)r0 * EMBED, rfc1w,
                                        mid + (size_t)r0 * FFN_DIM,
                                        m, FFN_DIM, EMBED, rfc1b, nullptr);
            dim3 g2(EMBED / 128, (m + 127) / 128);
            sgemm_nt<false><<<g2, 256>>>(mid + (size_t)r0 * FFN_DIM, rfc2w,
                                         out + (size_t)r0 * EMBED,
                                         m, EMBED, FFN_DIM, rfc2b,
                                         x1 + (size_t)r0 * EMBED);
        }
    }
}

// round 5
// speedup vs baseline: 2.9994x; 2.9994x over previous
#include <cuda_runtime.h>

// ---------------------------------------------------------------------------
// Problem constants (fixed by the reference setup)
// ---------------------------------------------------------------------------
#define EMBED    1024
#define HEADS    16
#define HEAD_DIM 64
#define FFN_DIM  4096
#define BSZ      2
#define SUM_LEN  16
#define REG_LEN  2048
#define TOTAL    (SUM_LEN + REG_LEN)   // 2064
#define NCHUNK   16
#define NTOK     (BSZ * TOTAL)         // 4128
#define MAXKEYS  144
#define ATTN_SMEM (MAXKEYS * HEAD_DIM * 2 * 4)

// ---------------------------------------------------------------------------
// Static device scratch (no cudaMalloc allowed)
// ---------------------------------------------------------------------------
__device__ float g_h  [(size_t)NTOK * EMBED];
__device__ float g_q  [(size_t)NTOK * EMBED];
__device__ float g_k  [(size_t)NTOK * EMBED];
__device__ float g_v  [(size_t)NTOK * EMBED];
__device__ float g_ctx[(size_t)NTOK * EMBED];
__device__ float g_x1 [(size_t)NTOK * EMBED];
__device__ float g_h2 [(size_t)NTOK * EMBED];
__device__ float g_mid[(size_t)NTOK * FFN_DIM];

// ---------------------------------------------------------------------------
// Helpers: tf32 rounding + mma.sync
// ---------------------------------------------------------------------------
__device__ __forceinline__ float f2tf32(float f) {
    unsigned u;
    asm("cvt.rna.tf32.f32 %0, %1;" : "=r"(u) : "f"(f));
    return __uint_as_float(u);
}
__device__ __forceinline__ float4 cvt4(float4 v) {
    return make_float4(f2tf32(v.x), f2tf32(v.y), f2tf32(v.z), f2tf32(v.w));
}
__device__ __forceinline__ void mma_tf32(float* d, const unsigned* a, const unsigned* b) {
    asm volatile(
        "mma.sync.aligned.m16n8k8.row.col.f32.tf32.tf32.f32 "
        "{%0,%1,%2,%3}, {%4,%5,%6,%7}, {%8,%9}, {%0,%1,%2,%3};"
        : "+f"(d[0]), "+f"(d[1]), "+f"(d[2]), "+f"(d[3])
        : "r"(a[0]), "r"(a[1]), "r"(a[2]), "r"(a[3]), "r"(b[0]), "r"(b[1]));
}

// ---------------------------------------------------------------------------
// TF32 tensor-core GEMM (NT): C[z][M,N] = op(A[z][M,K] @ B[N,K]^T + bias) + resid
// 128x128 tile, BK=16, 256 threads (8 warps in 4x2), m16n8k8 atoms.
// Smem rows padded to 20 floats -> bank-conflict-free fragment loads.
// gridDim = (N/128, ceil(M/128), nbatch); zA/zC/zR are per-z element offsets.
// ---------------------------------------------------------------------------
#define GSTRIDE 20

template<bool RELU, bool HAS_BIAS, bool HAS_RESID>
__global__ __launch_bounds__(256) void gemm_tf32(
    const float* __restrict__ A, const float* __restrict__ B,
    float* __restrict__ C, int M, int N, int K,
    const float* __restrict__ bias, const float* __restrict__ resid,
    size_t zA, size_t zC, size_t zR)
{
    __shared__ float As[2][128 * GSTRIDE];
    __shared__ float Bs[2][128 * GSTRIDE];

    A += (size_t)blockIdx.z * zA;
    C += (size_t)blockIdx.z * zC;
    if (HAS_RESID) resid += (size_t)blockIdx.z * zR;

    const int tid  = threadIdx.x;
    const int lane = tid & 31;
    const int warp = tid >> 5;
    const int wm   = (warp >> 1) * 32;   // warp row origin (0/32/64/96)
    const int wn   = (warp & 1) * 64;    // warp col origin (0/64)
    const int fr   = lane >> 2;          // 0..7
    const int fk   = lane & 3;           // 0..3

    // global load mapping: each thread owns row tid>>1, k-offset (tid&1)*8
    const int lrow = tid >> 1;
    const int lk   = (tid & 1) * 8;
    const int rowA = blockIdx.y * 128 + lrow;
    const bool aok = rowA < M;
    const float* Ag = A + (size_t)(aok ? rowA : 0) * K + lk;
    const float* Bg = B + (size_t)(blockIdx.x * 128 + lrow) * K + lk;
    float* as_dst0 = &As[0][lrow * GSTRIDE + lk];
    float* bs_dst0 = &Bs[0][lrow * GSTRIDE + lk];
    float* as_dst1 = &As[1][lrow * GSTRIDE + lk];
    float* bs_dst1 = &Bs[1][lrow * GSTRIDE + lk];

    float acc[2][8][4];
#pragma unroll
    for (int mt = 0; mt < 2; mt++)
#pragma unroll
        for (int nt = 0; nt < 8; nt++)
#pragma unroll
            for (int i = 0; i < 4; i++) acc[mt][nt][i] = 0.f;

    const float4 z4 = make_float4(0.f, 0.f, 0.f, 0.f);

    // prologue: stage tile 0
    {
        float4 a0 = aok ? *(const float4*)(Ag)     : z4;
        float4 a1 = aok ? *(const float4*)(Ag + 4) : z4;
        float4 b0 = *(const float4*)(Bg);
        float4 b1 = *(const float4*)(Bg + 4);
        *(float4*)(as_dst0)     = cvt4(a0);
        *(float4*)(as_dst0 + 4) = cvt4(a1);
        *(float4*)(bs_dst0)     = cvt4(b0);
        *(float4*)(bs_dst0 + 4) = cvt4(b1);
    }
    __syncthreads();

    const int nsteps = K >> 4;
    int buf = 0;
    for (int s = 0; s < nsteps; s++) {
        float4 na0, na1, nb0, nb1;
        const bool more = (s + 1 < nsteps);
        if (more) {
            int k0 = (s + 1) << 4;
            na0 = aok ? *(const float4*)(Ag + k0)     : z4;
            na1 = aok ? *(const float4*)(Ag + k0 + 4) : z4;
            nb0 = *(const float4*)(Bg + k0);
            nb1 = *(const float4*)(Bg + k0 + 4);
        }

        const float* asb = As[buf];
        const float* bsb = Bs[buf];
#pragma unroll
        for (int sub = 0; sub < 2; sub++) {
            const int kk = sub * 8 + fk;
            unsigned a[2][4];
#pragma unroll
            for (int mt = 0; mt < 2; mt++) {
                int base = (wm + mt * 16 + fr) * GSTRIDE;
                a[mt][0] = __float_as_uint(asb[base + kk]);
                a[mt][1] = __float_as_uint(asb[base + 8 * GSTRIDE + kk]);
                a[mt][2] = __float_as_uint(asb[base + kk + 4]);
                a[mt][3] = __float_as_uint(asb[base + 8 * GSTRIDE + kk + 4]);
            }
            unsigned b[8][2];
#pragma unroll
            for (int nt = 0; nt < 8; nt++) {
                int cb = (wn + nt * 8 + fr) * GSTRIDE;
                b[nt][0] = __float_as_uint(bsb[cb + kk]);
                b[nt][1] = __float_as_uint(bsb[cb + kk + 4]);
            }
#pragma unroll
            for (int mt = 0; mt < 2; mt++)
#pragma unroll
                for (int nt = 0; nt < 8; nt++)
                    mma_tf32(acc[mt][nt], a[mt], b[nt]);
        }

        if (more) {
            float* ad = (buf ? as_dst0 : as_dst1);
            float* bd = (buf ? bs_dst0 : bs_dst1);
            *(float4*)(ad)     = cvt4(na0);
            *(float4*)(ad + 4) = cvt4(na1);
            *(float4*)(bd)     = cvt4(nb0);
            *(float4*)(bd + 4) = cvt4(nb1);
        }
        __syncthreads();
        buf ^= 1;
    }

    // epilogue
    const int rowbase = blockIdx.y * 128 + wm + fr;
    const int colbase = blockIdx.x * 128 + wn + fk * 2;
#pragma unroll
    for (int mt = 0; mt < 2; mt++) {
#pragma unroll
        for (int half = 0; half < 2; half++) {
            int r = rowbase + mt * 16 + half * 8;
            if (r >= M) continue;
#pragma unroll
            for (int nt = 0; nt < 8; nt++) {
                int cidx = colbase + nt * 8;
                float v0 = acc[mt][nt][half * 2 + 0];
                float v1 = acc[mt][nt][half * 2 + 1];
                if (HAS_BIAS) { v0 += bias[cidx]; v1 += bias[cidx + 1]; }
                if (RELU) { v0 = fmaxf(v0, 0.f); v1 = fmaxf(v1, 0.f); }
                if (HAS_RESID) {
                    float2 rr = *(const float2*)(resid + (size_t)r * N + cidx);
                    v0 += rr.x; v1 += rr.y;
                }
                *(float2*)(C + (size_t)r * N + cidx) = make_float2(v0, v1);
            }
        }
    }
}

// ---------------------------------------------------------------------------
// LayerNorm: one block per row (1024 floats), 256 threads, float4 I/O.
// ---------------------------------------------------------------------------
__global__ __launch_bounds__(256) void ln_kernel(
    const float* __restrict__ x,
    const float* __restrict__ gs, const float* __restrict__ bs,
    const float* __restrict__ gr, const float* __restrict__ br,
    float* __restrict__ out)
{
    int row = blockIdx.x;
    int t = row % TOTAL;
    const float* g = (t < SUM_LEN) ? gs : gr;
    const float* b = (t < SUM_LEN) ? bs : br;
    int tid = threadIdx.x;
    int lane = tid & 31, warp = tid >> 5;

    float4 v = ((const float4*)(x + (size_t)row * EMBED))[tid];
    float s = v.x + v.y + v.z + v.w;
    float q = v.x * v.x + v.y * v.y + v.z * v.z + v.w * v.w;

    __shared__ float rs_[8], rq_[8];
#pragma unroll
    for (int o = 16; o; o >>= 1) {
        s += __shfl_xor_sync(0xffffffffu, s, o);
        q += __shfl_xor_sync(0xffffffffu, q, o);
    }
    if (lane == 0) { rs_[warp] = s; rq_[warp] = q; }
    __syncthreads();
    if (tid < 32) {
        s = (lane < 8) ? rs_[lane] : 0.f;
        q = (lane < 8) ? rq_[lane] : 0.f;
#pragma unroll
        for (int o = 4; o; o >>= 1) {
            s += __shfl_xor_sync(0xffffffffu, s, o);
            q += __shfl_xor_sync(0xffffffffu, q, o);
        }
        if (lane == 0) { rs_[0] = s; rq_[0] = q; }
    }
    __syncthreads();

    float mean = rs_[0] * (1.f / EMBED);
    float var  = rq_[0] * (1.f / EMBED) - mean * mean;
    float rinv = rsqrtf(var + 1e-5f);

    float4 gg = ((const float4*)g)[tid];
    float4 bb = ((const float4*)b)[tid];
    float4 o4;
    o4.x = (v.x - mean) * rinv * gg.x + bb.x;
    o4.y = (v.y - mean) * rinv * gg.y + bb.y;
    o4.z = (v.z - mean) * rinv * gg.z + bb.z;
    o4.w = (v.w - mean) * rinv * gg.w + bb.w;
    ((float4*)(out + (size_t)row * EMBED))[tid] = o4;
}

// ---------------------------------------------------------------------------
// Attention for REG queries. Grid (NCHUNK, HEADS, BSZ), 128 threads.
// ---------------------------------------------------------------------------
__global__ void attn_reg_kernel(
    const float* __restrict__ Q, const float* __restrict__ K,
    const float* __restrict__ V, const int* __restrict__ ranges,
    float* __restrict__ CTX)
{
    extern __shared__ float sm[];
    float* Ks = sm;
    float* Vs = sm + MAXKEYS * HEAD_DIM;

    int c = blockIdx.x, h = blockIdx.y, b = blockIdx.z;
    int start = ranges[(b * NCHUNK + c) * 2];
    int next  = (c + 1 < NCHUNK) ? ranges[(b * NCHUNK + c + 1) * 2] : REG_LEN;
    int width = next - start;
    int nsum  = c;
    int nk    = nsum + width;

    for (int idx = threadIdx.x; idx < nk * 16; idx += 128) {
        int j = idx >> 4, f = idx & 15;
        int tok = (j < nsum) ? j : (SUM_LEN + start + (j - nsum));
        size_t off = ((size_t)b * TOTAL + tok) * EMBED + h * HEAD_DIM;
        ((float4*)Ks)[j * 16 + f] = ((const float4*)(K + off))[f];
        ((float4*)Vs)[j * 16 + f] = ((const float4*)(V + off))[f];
    }
    __syncthreads();

    for (int qi = threadIdx.x; qi < width; qi += 128) {
        int tq = SUM_LEN + start + qi;
        const float4* qp = (const float4*)(Q + ((size_t)b * TOTAL + tq) * EMBED + h * HEAD_DIM);
        float qreg[64];
#pragma unroll
        for (int f = 0; f < 16; f++) {
            float4 t4 = qp[f];
            qreg[4 * f + 0] = t4.x * 0.125f;
            qreg[4 * f + 1] = t4.y * 0.125f;
            qreg[4 * f + 2] = t4.z * 0.125f;
            qreg[4 * f + 3] = t4.w * 0.125f;
        }
        float m = -1e30f, l = 0.f;
        float ctx[64];
#pragma unroll
        for (int d = 0; d < 64; d++) ctx[d] = 0.f;

        int jmax = nsum + qi + 1;
        for (int j = 0; j < jmax; j++) {
            const float4* kj = (const float4*)(Ks + j * HEAD_DIM);
            float s0 = 0.f, s1 = 0.f, s2 = 0.f, s3 = 0.f;
#pragma unroll
            for (int f = 0; f < 16; f++) {
                float4 kk = kj[f];
                s0 = fmaf(qreg[4 * f + 0], kk.x, s0);
                s1 = fmaf(qreg[4 * f + 1], kk.y, s1);
                s2 = fmaf(qreg[4 * f + 2], kk.z, s2);
                s3 = fmaf(qreg[4 * f + 3], kk.w, s3);
            }
            float sdot = (s0 + s1) + (s2 + s3);
            float mn = fmaxf(m, sdot);
            float alpha = __expf(m - mn);
            float p = __expf(sdot - mn);
            l = l * alpha + p;
            const float4* vj = (const float4*)(Vs + j * HEAD_DIM);
#pragma unroll
            for (int f = 0; f < 16; f++) {
                float4 vv = vj[f];
                ctx[4 * f + 0] = fmaf(p, vv.x, ctx[4 * f + 0] * alpha);
                ctx[4 * f + 1] = fmaf(p, vv.y, ctx[4 * f + 1] * alpha);
                ctx[4 * f + 2] = fmaf(p, vv.z, ctx[4 * f + 2] * alpha);
                ctx[4 * f + 3] = fmaf(p, vv.w, ctx[4 * f + 3] * alpha);
            }
            m = mn;
        }
        float inv = 1.f / l;
        float4* op = (float4*)(CTX + ((size_t)b * TOTAL + tq) * EMBED + h * HEAD_DIM);
#pragma unroll
        for (int f = 0; f < 16; f++)
            op[f] = make_float4(ctx[4 * f + 0] * inv, ctx[4 * f + 1] * inv,
                                ctx[4 * f + 2] * inv, ctx[4 * f + 3] * inv);
    }
}

// ---------------------------------------------------------------------------
// Attention for SUM queries. One warp per (b, h, s).
// ---------------------------------------------------------------------------
__global__ __launch_bounds__(256) void attn_sum_kernel(
    const float* __restrict__ Q, const float* __restrict__ K,
    const float* __restrict__ V, const int* __restrict__ ranges,
    float* __restrict__ CTX)
{
    int gw = (blockIdx.x * blockDim.x + threadIdx.x) >> 5;
    int lane = threadIdx.x & 31;
    if (gw >= BSZ * HEADS * SUM_LEN) return;
    int b = gw / (HEADS * SUM_LEN);
    int rem = gw % (HEADS * SUM_LEN);
    int h = rem / SUM_LEN;
    int s = rem % SUM_LEN;

    int start = ranges[(b * NCHUNK + s) * 2];
    int next  = (s + 1 < NCHUNK) ? ranges[(b * NCHUNK + s + 1) * 2] : REG_LEN;

    size_t bbase = (size_t)b * TOTAL;
    float2 q2 = ((const float2*)(Q + (bbase + s) * EMBED + h * HEAD_DIM))[lane];
    q2.x *= 0.125f; q2.y *= 0.125f;

    float m = -1e30f, l = 0.f, cx = 0.f, cy = 0.f;

#define ATTN_SUM_STEP(tok_expr)                                                        \
    do {                                                                               \
        int tok = (tok_expr);                                                          \
        float2 kk = ((const float2*)(K + (bbase + tok) * EMBED + h * HEAD_DIM))[lane]; \
        float part = q2.x * kk.x + q2.y * kk.y;                                        \
        _Pragma("unroll")                                                              \
        for (int o = 16; o; o >>= 1) part += __shfl_xor_sync(0xffffffffu, part, o);    \
        float mn = fmaxf(m, part);                                                     \
        float alpha = __expf(m - mn);                                                  \
        float p = __expf(part - mn);                                                   \
        l = l * alpha + p;                                                             \
        float2 vv = ((const float2*)(V + (bbase + tok) * EMBED + h * HEAD_DIM))[lane]; \
        cx = fmaf(p, vv.x, cx * alpha);                                                \
        cy = fmaf(p, vv.y, cy * alpha);                                                \
        m = mn;                                                                        \
    } while (0)

    for (int t = 0; t <= s; t++)       ATTN_SUM_STEP(t);
    for (int t = start; t < next; t++) ATTN_SUM_STEP(SUM_LEN + t);

#undef ATTN_SUM_STEP

    float inv = 1.f / l;
    ((float2*)(CTX + (bbase + s) * EMBED + h * HEAD_DIM))[lane] =
        make_float2(cx * inv, cy * inv);
}

// ---------------------------------------------------------------------------
// Launch sequence
// ---------------------------------------------------------------------------
extern "C" void kernel_launch(void* const* d_in, const int* in_sizes, int n_in,
                              void* d_out, int out_size)
{
    const float* x      = (const float*)d_in[0];
    const float* w_q    = (const float*)d_in[1];
    const float* w_k    = (const float*)d_in[2];
    const float* w_v    = (const float*)d_in[3];
    const float* w_o    = (const float*)d_in[4];
    const float* ln1_sg = (const float*)d_in[5];
    const float* ln1_sb = (const float*)d_in[6];
    const float* ln1_rg = (const float*)d_in[7];
    const float* ln1_rb = (const float*)d_in[8];
    const float* sfc1w  = (const float*)d_in[9];
    const float* sfc1b  = (const float*)d_in[10];
    const float* sfc2w  = (const float*)d_in[11];
    const float* sfc2b  = (const float*)d_in[12];
    const float* rfc1w  = (const float*)d_in[13];
    const float* rfc1b  = (const float*)d_in[14];
    const float* rfc2w  = (const float*)d_in[15];
    const float* rfc2b  = (const float*)d_in[16];
    const float* ln2_sg = (const float*)d_in[17];
    const float* ln2_sb = (const float*)d_in[18];
    const float* ln2_rg = (const float*)d_in[19];
    const float* ln2_rb = (const float*)d_in[20];
    const int*   ranges = (const int*)d_in[21];
    float* out = (float*)d_out;

    void *ph, *pq, *pk, *pv, *pctx, *px1, *ph2, *pmid;
    cudaGetSymbolAddress(&ph,   g_h);
    cudaGetSymbolAddress(&pq,   g_q);
    cudaGetSymbolAddress(&pk,   g_k);
    cudaGetSymbolAddress(&pv,   g_v);
    cudaGetSymbolAddress(&pctx, g_ctx);
    cudaGetSymbolAddress(&px1,  g_x1);
    cudaGetSymbolAddress(&ph2,  g_h2);
    cudaGetSymbolAddress(&pmid, g_mid);
    float* h   = (float*)ph;
    float* q   = (float*)pq;
    float* k   = (float*)pk;
    float* v   = (float*)pv;
    float* ctx = (float*)pctx;
    float* x1  = (float*)px1;
    float* h2  = (float*)ph2;
    float* mid = (float*)pmid;

    cudaFuncSetAttribute(attn_reg_kernel,
                         cudaFuncAttributeMaxDynamicSharedMemorySize, ATTN_SMEM);

    // 1) LN1
    ln_kernel<<<NTOK, 256>>>(x, ln1_sg, ln1_sb, ln1_rg, ln1_rb, h);

    // 2) QKV projections: M=4128, N=1024, K=1024
    dim3 gP(EMBED / 128, (NTOK + 127) / 128, 1);
    gemm_tf32<false, false, false><<<gP, 256>>>(h, w_q, q, NTOK, EMBED, EMBED,
                                                nullptr, nullptr, 0, 0, 0);
    gemm_tf32<false, false, false><<<gP, 256>>>(h, w_k, k, NTOK, EMBED, EMBED,
                                                nullptr, nullptr, 0, 0, 0);
    gemm_tf32<false, false, false><<<gP, 256>>>(h, w_v, v, NTOK, EMBED, EMBED,
                                                nullptr, nullptr, 0, 0, 0);

    // 3) Sparse masked attention
    attn_reg_kernel<<<dim3(NCHUNK, HEADS, BSZ), 128, ATTN_SMEM>>>(q, k, v, ranges, ctx);
    attn_sum_kernel<<<(BSZ * HEADS * SUM_LEN) / 8, 256>>>(q, k, v, ranges, ctx);

    // 4) Output projection + residual: x1 = x + ctx @ Wo^T
    gemm_tf32<false, false, true><<<gP, 256>>>(ctx, w_o, x1, NTOK, EMBED, EMBED,
                                               nullptr, x, 0, 0, 0);

    // 5) LN2
    ln_kernel<<<NTOK, 256>>>(x1, ln2_sg, ln2_sb, ln2_rg, ln2_rb, h2);

    // 6) FFN — reg segments batched over z (M=2048 each)
    {
        const size_t zE = (size_t)TOTAL * EMBED;
        const size_t zF = (size_t)TOTAL * FFN_DIM;
        const float* a1 = h2  + (size_t)SUM_LEN * EMBED;
        float*       m1 = mid + (size_t)SUM_LEN * FFN_DIM;
        float*       o1 = out + (size_t)SUM_LEN * EMBED;
        const float* r1 = x1  + (size_t)SUM_LEN * EMBED;

        dim3 g1(FFN_DIM / 128, REG_LEN / 128, BSZ);
        gemm_tf32<true, true, false><<<g1, 256>>>(a1, rfc1w, m1, REG_LEN, FFN_DIM, EMBED,
                                                  rfc1b, nullptr, zE, zF, 0);
        dim3 g2(EMBED / 128, REG_LEN / 128, BSZ);
        gemm_tf32<false, true, true><<<g2, 256>>>(m1, rfc2w, o1, REG_LEN, EMBED, FFN_DIM,
                                                  rfc2b, r1, zF, zE, zE);

        // sum segments (M=16 each), batched over z
        dim3 g3(FFN_DIM / 128, 1, BSZ);
        gemm_tf32<true, true, false><<<g3, 256>>>(h2, sfc1w, mid, SUM_LEN, FFN_DIM, EMBED,
                                                  sfc1b, nullptr, zE, zF, 0);
        dim3 g4(EMBED / 128, 1, BSZ);
        gemm_tf32<false, true, true><<<g4, 256>>>(mid, sfc2w, out, SUM_LEN, EMBED, FFN_DIM,
                                                  sfc2b, x1, zF, zE, zE);
    }
}

// round 6
// speedup vs baseline: 3.0066x; 1.0024x over previous
#include <cuda_runtime.h>

// ---------------------------------------------------------------------------
// Problem constants (fixed by the reference setup)
// ---------------------------------------------------------------------------
#define EMBED    1024
#define HEADS    16
#define HEAD_DIM 64
#define FFN_DIM  4096
#define BSZ      2
#define SUM_LEN  16
#define REG_LEN  2048
#define TOTAL    (SUM_LEN + REG_LEN)   // 2064
#define NCHUNK   16
#define NTOK     (BSZ * TOTAL)         // 4128
#define MAXKEYS  144
#define ATTN_SMEM (MAXKEYS * HEAD_DIM * 2 * 4)

// ---------------------------------------------------------------------------
// Static device scratch (no cudaMalloc allowed)
// ---------------------------------------------------------------------------
__device__ float g_h  [(size_t)NTOK * EMBED];
__device__ float g_q  [(size_t)NTOK * EMBED];
__device__ float g_k  [(size_t)NTOK * EMBED];
__device__ float g_v  [(size_t)NTOK * EMBED];
__device__ float g_ctx[(size_t)NTOK * EMBED];
__device__ float g_x1 [(size_t)NTOK * EMBED];
__device__ float g_h2 [(size_t)NTOK * EMBED];
__device__ float g_mid[(size_t)NTOK * FFN_DIM];

// ---------------------------------------------------------------------------
// Helpers: tf32 rounding + mma.sync
// ---------------------------------------------------------------------------
__device__ __forceinline__ float f2tf32(float f) {
    unsigned u;
    asm("cvt.rna.tf32.f32 %0, %1;" : "=r"(u) : "f"(f));
    return __uint_as_float(u);
}
__device__ __forceinline__ float4 cvt4(float4 v) {
    return make_float4(f2tf32(v.x), f2tf32(v.y), f2tf32(v.z), f2tf32(v.w));
}
__device__ __forceinline__ void mma_tf32(float* d, const unsigned* a, const unsigned* b) {
    asm volatile(
        "mma.sync.aligned.m16n8k8.row.col.f32.tf32.tf32.f32 "
        "{%0,%1,%2,%3}, {%4,%5,%6,%7}, {%8,%9}, {%0,%1,%2,%3};"
        : "+f"(d[0]), "+f"(d[1]), "+f"(d[2]), "+f"(d[3])
        : "r"(a[0]), "r"(a[1]), "r"(a[2]), "r"(a[3]), "r"(b[0]), "r"(b[1]));
}

// ---------------------------------------------------------------------------
// TF32 tensor-core GEMM (NT): C[z][M,N] = op(A[z][M,K] @ B[N,K]^T + bias) + resid
// 128x128 tile, BK=16, 256 threads (8 warps in 4x2), m16n8k8 atoms.
// Smem rows padded to 20 floats -> bank-conflict-free fragment loads.
// gridDim = (N/128, ceil(M/128), nbatch); zA/zC/zR are per-z element offsets.
// ---------------------------------------------------------------------------
#define GSTRIDE 20

template<bool RELU, bool HAS_BIAS, bool HAS_RESID>
__global__ __launch_bounds__(256) void gemm_tf32(
    const float* __restrict__ A, const float* __restrict__ B,
    float* __restrict__ C, int M, int N, int K,
    const float* __restrict__ bias, const float* __restrict__ resid,
    size_t zA, size_t zC, size_t zR)
{
    __shared__ float As[2][128 * GSTRIDE];
    __shared__ float Bs[2][128 * GSTRIDE];

    A += (size_t)blockIdx.z * zA;
    C += (size_t)blockIdx.z * zC;
    if (HAS_RESID) resid += (size_t)blockIdx.z * zR;

    const int tid  = threadIdx.x;
    const int lane = tid & 31;
    const int warp = tid >> 5;
    const int wm   = (warp >> 1) * 32;   // warp row origin (0/32/64/96)
    const int wn   = (warp & 1) * 64;    // warp col origin (0/64)
    const int fr   = lane >> 2;          // 0..7
    const int fk   = lane & 3;           // 0..3

    // global load mapping: each thread owns row tid>>1, k-offset (tid&1)*8
    const int lrow = tid >> 1;
    const int lk   = (tid & 1) * 8;
    const int rowA = blockIdx.y * 128 + lrow;
    const bool aok = rowA < M;
    const float* Ag = A + (size_t)(aok ? rowA : 0) * K + lk;
    const float* Bg = B + (size_t)(blockIdx.x * 128 + lrow) * K + lk;
    float* as_dst0 = &As[0][lrow * GSTRIDE + lk];
    float* bs_dst0 = &Bs[0][lrow * GSTRIDE + lk];
    float* as_dst1 = &As[1][lrow * GSTRIDE + lk];
    float* bs_dst1 = &Bs[1][lrow * GSTRIDE + lk];

    float acc[2][8][4];
#pragma unroll
    for (int mt = 0; mt < 2; mt++)
#pragma unroll
        for (int nt = 0; nt < 8; nt++)
#pragma unroll
            for (int i = 0; i < 4; i++) acc[mt][nt][i] = 0.f;

    const float4 z4 = make_float4(0.f, 0.f, 0.f, 0.f);

    // prologue: stage tile 0
    {
        float4 a0 = aok ? *(const float4*)(Ag)     : z4;
        float4 a1 = aok ? *(const float4*)(Ag + 4) : z4;
        float4 b0 = *(const float4*)(Bg);
        float4 b1 = *(const float4*)(Bg + 4);
        *(float4*)(as_dst0)     = cvt4(a0);
        *(float4*)(as_dst0 + 4) = cvt4(a1);
        *(float4*)(bs_dst0)     = cvt4(b0);
        *(float4*)(bs_dst0 + 4) = cvt4(b1);
    }
    __syncthreads();

    const int nsteps = K >> 4;
    int buf = 0;
    for (int s = 0; s < nsteps; s++) {
        float4 na0, na1, nb0, nb1;
        const bool more = (s + 1 < nsteps);
        if (more) {
            int k0 = (s + 1) << 4;
            na0 = aok ? *(const float4*)(Ag + k0)     : z4;
            na1 = aok ? *(const float4*)(Ag + k0 + 4) : z4;
            nb0 = *(const float4*)(Bg + k0);
            nb1 = *(const float4*)(Bg + k0 + 4);
        }

        const float* asb = As[buf];
        const float* bsb = Bs[buf];
#pragma unroll
        for (int sub = 0; sub < 2; sub++) {
            const int kk = sub * 8 + fk;
            unsigned a[2][4];
#pragma unroll
            for (int mt = 0; mt < 2; mt++) {
                int base = (wm + mt * 16 + fr) * GSTRIDE;
                a[mt][0] = __float_as_uint(asb[base + kk]);
                a[mt][1] = __float_as_uint(asb[base + 8 * GSTRIDE + kk]);
                a[mt][2] = __float_as_uint(asb[base + kk + 4]);
                a[mt][3] = __float_as_uint(asb[base + 8 * GSTRIDE + kk + 4]);
            }
            unsigned b[8][2];
#pragma unroll
            for (int nt = 0; nt < 8; nt++) {
                int cb = (wn + nt * 8 + fr) * GSTRIDE;
                b[nt][0] = __float_as_uint(bsb[cb + kk]);
                b[nt][1] = __float_as_uint(bsb[cb + kk + 4]);
            }
#pragma unroll
            for (int mt = 0; mt < 2; mt++)
#pragma unroll
                for (int nt = 0; nt < 8; nt++)
                    mma_tf32(acc[mt][nt], a[mt], b[nt]);
        }

        if (more) {
            float* ad = (buf ? as_dst0 : as_dst1);
            float* bd = (buf ? bs_dst0 : bs_dst1);
            *(float4*)(ad)     = cvt4(na0);
            *(float4*)(ad + 4) = cvt4(na1);
            *(float4*)(bd)     = cvt4(nb0);
            *(float4*)(bd + 4) = cvt4(nb1);
        }
        __syncthreads();
        buf ^= 1;
    }

    // epilogue
    const int rowbase = blockIdx.y * 128 + wm + fr;
    const int colbase = blockIdx.x * 128 + wn + fk * 2;
#pragma unroll
    for (int mt = 0; mt < 2; mt++) {
#pragma unroll
        for (int half = 0; half < 2; half++) {
            int r = rowbase + mt * 16 + half * 8;
            if (r >= M) continue;
#pragma unroll
            for (int nt = 0; nt < 8; nt++) {
                int cidx = colbase + nt * 8;
                float v0 = acc[mt][nt][half * 2 + 0];
                float v1 = acc[mt][nt][half * 2 + 1];
                if (HAS_BIAS) { v0 += bias[cidx]; v1 += bias[cidx + 1]; }
                if (RELU) { v0 = fmaxf(v0, 0.f); v1 = fmaxf(v1, 0.f); }
                if (HAS_RESID) {
                    float2 rr = *(const float2*)(resid + (size_t)r * N + cidx);
                    v0 += rr.x; v1 += rr.y;
                }
                *(float2*)(C + (size_t)r * N + cidx) = make_float2(v0, v1);
            }
        }
    }
}

// ---------------------------------------------------------------------------
// LayerNorm: one block per row (1024 floats), 256 threads, float4 I/O.
// ---------------------------------------------------------------------------
__global__ __launch_bounds__(256) void ln_kernel(
    const float* __restrict__ x,
    const float* __restrict__ gs, const float* __restrict__ bs,
    const float* __restrict__ gr, const float* __restrict__ br,
    float* __restrict__ out)
{
    int row = blockIdx.x;
    int t = row % TOTAL;
    const float* g = (t < SUM_LEN) ? gs : gr;
    const float* b = (t < SUM_LEN) ? bs : br;
    int tid = threadIdx.x;
    int lane = tid & 31, warp = tid >> 5;

    float4 v = ((const float4*)(x + (size_t)row * EMBED))[tid];
    float s = v.x + v.y + v.z + v.w;
    float q = v.x * v.x + v.y * v.y + v.z * v.z + v.w * v.w;

    __shared__ float rs_[8], rq_[8];
#pragma unroll
    for (int o = 16; o; o >>= 1) {
        s += __shfl_xor_sync(0xffffffffu, s, o);
        q += __shfl_xor_sync(0xffffffffu, q, o);
    }
    if (lane == 0) { rs_[warp] = s; rq_[warp] = q; }
    __syncthreads();
    if (tid < 32) {
        s = (lane < 8) ? rs_[lane] : 0.f;
        q = (lane < 8) ? rq_[lane] : 0.f;
#pragma unroll
        for (int o = 4; o; o >>= 1) {
            s += __shfl_xor_sync(0xffffffffu, s, o);
            q += __shfl_xor_sync(0xffffffffu, q, o);
        }
        if (lane == 0) { rs_[0] = s; rq_[0] = q; }
    }
    __syncthreads();

    float mean = rs_[0] * (1.f / EMBED);
    float var  = rq_[0] * (1.f / EMBED) - mean * mean;
    float rinv = rsqrtf(var + 1e-5f);

    float4 gg = ((const float4*)g)[tid];
    float4 bb = ((const float4*)b)[tid];
    float4 o4;
    o4.x = (v.x - mean) * rinv * gg.x + bb.x;
    o4.y = (v.y - mean) * rinv * gg.y + bb.y;
    o4.z = (v.z - mean) * rinv * gg.z + bb.z;
    o4.w = (v.w - mean) * rinv * gg.w + bb.w;
    ((float4*)(out + (size_t)row * EMBED))[tid] = o4;
}

// ---------------------------------------------------------------------------
// Attention for REG queries. Grid (NCHUNK, HEADS, BSZ), 128 threads.
// ---------------------------------------------------------------------------
__global__ void attn_reg_kernel(
    const float* __restrict__ Q, const float* __restrict__ K,
    const float* __restrict__ V, const int* __restrict__ ranges,
    float* __restrict__ CTX)
{
    extern __shared__ float sm[];
    float* Ks = sm;
    float* Vs = sm + MAXKEYS * HEAD_DIM;

    int c = blockIdx.x, h = blockIdx.y, b = blockIdx.z;
    int start = ranges[(b * NCHUNK + c) * 2];
    int next  = (c + 1 < NCHUNK) ? ranges[(b * NCHUNK + c + 1) * 2] : REG_LEN;
    int width = next - start;
    int nsum  = c;
    int nk    = nsum + width;

    for (int idx = threadIdx.x; idx < nk * 16; idx += 128) {
        int j = idx >> 4, f = idx & 15;
        int tok = (j < nsum) ? j : (SUM_LEN + start + (j - nsum));
        size_t off = ((size_t)b * TOTAL + tok) * EMBED + h * HEAD_DIM;
        ((float4*)Ks)[j * 16 + f] = ((const float4*)(K + off))[f];
        ((float4*)Vs)[j * 16 + f] = ((const float4*)(V + off))[f];
    }
    __syncthreads();

    for (int qi = threadIdx.x; qi < width; qi += 128) {
        int tq = SUM_LEN + start + qi;
        const float4* qp = (const float4*)(Q + ((size_t)b * TOTAL + tq) * EMBED + h * HEAD_DIM);
        float qreg[64];
#pragma unroll
        for (int f = 0; f < 16; f++) {
            float4 t4 = qp[f];
            qreg[4 * f + 0] = t4.x * 0.125f;
            qreg[4 * f + 1] = t4.y * 0.125f;
            qreg[4 * f + 2] = t4.z * 0.125f;
            qreg[4 * f + 3] = t4.w * 0.125f;
        }
        float m = -1e30f, l = 0.f;
        float ctx[64];
#pragma unroll
        for (int d = 0; d < 64; d++) ctx[d] = 0.f;

        int jmax = nsum + qi + 1;
        for (int j = 0; j < jmax; j++) {
            const float4* kj = (const float4*)(Ks + j * HEAD_DIM);
            float s0 = 0.f, s1 = 0.f, s2 = 0.f, s3 = 0.f;
#pragma unroll
            for (int f = 0; f < 16; f++) {
                float4 kk = kj[f];
                s0 = fmaf(qreg[4 * f + 0], kk.x, s0);
                s1 = fmaf(qreg[4 * f + 1], kk.y, s1);
                s2 = fmaf(qreg[4 * f + 2], kk.z, s2);
                s3 = fmaf(qreg[4 * f + 3], kk.w, s3);
            }
            float sdot = (s0 + s1) + (s2 + s3);
            float mn = fmaxf(m, sdot);
            float alpha = __expf(m - mn);
            float p = __expf(sdot - mn);
            l = l * alpha + p;
            const float4* vj = (const float4*)(Vs + j * HEAD_DIM);
#pragma unroll
            for (int f = 0; f < 16; f++) {
                float4 vv = vj[f];
                ctx[4 * f + 0] = fmaf(p, vv.x, ctx[4 * f + 0] * alpha);
                ctx[4 * f + 1] = fmaf(p, vv.y, ctx[4 * f + 1] * alpha);
                ctx[4 * f + 2] = fmaf(p, vv.z, ctx[4 * f + 2] * alpha);
                ctx[4 * f + 3] = fmaf(p, vv.w, ctx[4 * f + 3] * alpha);
            }
            m = mn;
        }
        float inv = 1.f / l;
        float4* op = (float4*)(CTX + ((size_t)b * TOTAL + tq) * EMBED + h * HEAD_DIM);
#pragma unroll
        for (int f = 0; f < 16; f++)
            op[f] = make_float4(ctx[4 * f + 0] * inv, ctx[4 * f + 1] * inv,
                                ctx[4 * f + 2] * inv, ctx[4 * f + 3] * inv);
    }
}

// ---------------------------------------------------------------------------
// Attention for SUM queries. One warp per (b, h, s).
// ---------------------------------------------------------------------------
__global__ __launch_bounds__(256) void attn_sum_kernel(
    const float* __restrict__ Q, const float* __restrict__ K,
    const float* __restrict__ V, const int* __restrict__ ranges,
    float* __restrict__ CTX)
{
    int gw = (blockIdx.x * blockDim.x + threadIdx.x) >> 5;
    int lane = threadIdx.x & 31;
    if (gw >= BSZ * HEADS * SUM_LEN) return;
    int b = gw / (HEADS * SUM_LEN);
    int rem = gw % (HEADS * SUM_LEN);
    int h = rem / SUM_LEN;
    int s = rem % SUM_LEN;

    int start = ranges[(b * NCHUNK + s) * 2];
    int next  = (s + 1 < NCHUNK) ? ranges[(b * NCHUNK + s + 1) * 2] : REG_LEN;

    size_t bbase = (size_t)b * TOTAL;
    float2 q2 = ((const float2*)(Q + (bbase + s) * EMBED + h * HEAD_DIM))[lane];
    q2.x *= 0.125f; q2.y *= 0.125f;

    float m = -1e30f, l = 0.f, cx = 0.f, cy = 0.f;

#define ATTN_SUM_STEP(tok_expr)                                                        \
    do {                                                                               \
        int tok = (tok_expr);                                                          \
        float2 kk = ((const float2*)(K + (bbase + tok) * EMBED + h * HEAD_DIM))[lane]; \
        float part = q2.x * kk.x + q2.y * kk.y;                                        \
        _Pragma("unroll")                                                              \
        for (int o = 16; o; o >>= 1) part += __shfl_xor_sync(0xffffffffu, part, o);    \
        float mn = fmaxf(m, part);                                                     \
        float alpha = __expf(m - mn);                                                  \
        float p = __expf(part - mn);                                                   \
        l = l * alpha + p;                                                             \
        float2 vv = ((const float2*)(V + (bbase + tok) * EMBED + h * HEAD_DIM))[lane]; \
        cx = fmaf(p, vv.x, cx * alpha);                                                \
        cy = fmaf(p, vv.y, cy * alpha);                                                \
        m = mn;                                                                        \
    } while (0)

    for (int t = 0; t <= s; t++)       ATTN_SUM_STEP(t);
    for (int t = start; t < next; t++) ATTN_SUM_STEP(SUM_LEN + t);

#undef ATTN_SUM_STEP

    float inv = 1.f / l;
    ((float2*)(CTX + (bbase + s) * EMBED + h * HEAD_DIM))[lane] =
        make_float2(cx * inv, cy * inv);
}

// ---------------------------------------------------------------------------
// Launch sequence
// ---------------------------------------------------------------------------
extern "C" void kernel_launch(void* const* d_in, const int* in_sizes, int n_in,
                              void* d_out, int out_size)
{
    const float* x      = (const float*)d_in[0];
    const float* w_q    = (const float*)d_in[1];
    const float* w_k    = (const float*)d_in[2];
    const float* w_v    = (const float*)d_in[3];
    const float* w_o    = (const float*)d_in[4];
    const float* ln1_sg = (const float*)d_in[5];
    const float* ln1_sb = (const float*)d_in[6];
    const float* ln1_rg = (const float*)d_in[7];
    const float* ln1_rb = (const float*)d_in[8];
    const float* sfc1w  = (const float*)d_in[9];
    const float* sfc1b  = (const float*)d_in[10];
    const float* sfc2w  = (const float*)d_in[11];
    const float* sfc2b  = (const float*)d_in[12];
    const float* rfc1w  = (const float*)d_in[13];
    const float* rfc1b  = (const float*)d_in[14];
    const float* rfc2w  = (const float*)d_in[15];
    const float* rfc2b  = (const float*)d_in[16];
    const float* ln2_sg = (const float*)d_in[17];
    const float* ln2_sb = (const float*)d_in[18];
    const float* ln2_rg = (const float*)d_in[19];
    const float* ln2_rb = (const float*)d_in[20];
    const int*   ranges = (const int*)d_in[21];
    float* out = (float*)d_out;

    void *ph, *pq, *pk, *pv, *pctx, *px1, *ph2, *pmid;
    cudaGetSymbolAddress(&ph,   g_h);
    cudaGetSymbolAddress(&pq,   g_q);
    cudaGetSymbolAddress(&pk,   g_k);
    cudaGetSymbolAddress(&pv,   g_v);
    cudaGetSymbolAddress(&pctx, g_ctx);
    cudaGetSymbolAddress(&px1,  g_x1);
    cudaGetSymbolAddress(&ph2,  g_h2);
    cudaGetSymbolAddress(&pmid, g_mid);
    float* h   = (float*)ph;
    float* q   = (float*)pq;
    float* k   = (float*)pk;
    float* v   = (float*)pv;
    float* ctx = (float*)pctx;
    float* x1  = (float*)px1;
    float* h2  = (float*)ph2;
    float* mid = (float*)pmid;

    cudaFuncSetAttribute(attn_reg_kernel,
                         cudaFuncAttributeMaxDynamicSharedMemorySize, ATTN_SMEM);

    // 1) LN1
    ln_kernel<<<NTOK, 256>>>(x, ln1_sg, ln1_sb, ln1_rg, ln1_rb, h);

    // 2) QKV projections: M=4128, N=1024, K=1024
    dim3 gP(EMBED / 128, (NTOK + 127) / 128, 1);
    gemm_tf32<false, false, false><<<gP, 256>>>(h, w_q, q, NTOK, EMBED, EMBED,
                                                nullptr, nullptr, 0, 0, 0);
    gemm_tf32<false, false, false><<<gP, 256>>>(h, w_k, k, NTOK, EMBED, EMBED,
                                                nullptr, nullptr, 0, 0, 0);
    gemm_tf32<false, false, false><<<gP, 256>>>(h, w_v, v, NTOK, EMBED, EMBED,
                                                nullptr, nullptr, 0, 0, 0);

    // 3) Sparse masked attention
    attn_reg_kernel<<<dim3(NCHUNK, HEADS, BSZ), 128, ATTN_SMEM>>>(q, k, v, ranges, ctx);
    attn_sum_kernel<<<(BSZ * HEADS * SUM_LEN) / 8, 256>>>(q, k, v, ranges, ctx);

    // 4) Output projection + residual: x1 = x + ctx @ Wo^T
    gemm_tf32<false, false, true><<<gP, 256>>>(ctx, w_o, x1, NTOK, EMBED, EMBED,
                                               nullptr, x, 0, 0, 0);

    // 5) LN2
    ln_kernel<<<NTOK, 256>>>(x1, ln2_sg, ln2_sb, ln2_rg, ln2_rb, h2);

    // 6) FFN — reg segments batched over z (M=2048 each)
    {
        const size_t zE = (size_t)TOTAL * EMBED;
        const size_t zF = (size_t)TOTAL * FFN_DIM;
        const float* a1 = h2  + (size_t)SUM_LEN * EMBED;
        float*       m1 = mid + (size_t)SUM_LEN * FFN_DIM;
        float*       o1 = out + (size_t)SUM_LEN * EMBED;
        const float* r1 = x1  + (size_t)SUM_LEN * EMBED;

        dim3 g1(FFN_DIM / 128, REG_LEN / 128, BSZ);
        gemm_tf32<true, true, false><<<g1, 256>>>(a1, rfc1w, m1, REG_LEN, FFN_DIM, EMBED,
                                                  rfc1b, nullptr, zE, zF, 0);
        dim3 g2(EMBED / 128, REG_LEN / 128, BSZ);
        gemm_tf32<false, true, true><<<g2, 256>>>(m1, rfc2w, o1, REG_LEN, EMBED, FFN_DIM,
                                                  rfc2b, r1, zF, zE, zE);

        // sum segments (M=16 each), batched over z
        dim3 g3(FFN_DIM / 128, 1, BSZ);
        gemm_tf32<true, true, false><<<g3, 256>>>(h2, sfc1w, mid, SUM_LEN, FFN_DIM, EMBED,
                                                  sfc1b, nullptr, zE, zF, 0);
        dim3 g4(EMBED / 128, 1, BSZ);
        gemm_tf32<false, true, true><<<g4, 256>>>(mid, sfc2w, out, SUM_LEN, EMBED, FFN_DIM,
                                                  sfc2b, x1, zF, zE, zE);
    }
}

// round 8
// speedup vs baseline: 4.1400x; 1.3770x over previous
#include <cuda_runtime.h>
#include <cstdint>
#include <cstddef>

// ---------------------------------------------------------------------------
#define EMBED    1024
#define HEADS    16
#define HEAD_DIM 64
#define FFN_DIM  4096
#define BSZ      2
#define SUM_LEN  16
#define REG_LEN  2048
#define TOTAL    (SUM_LEN + REG_LEN)   // 2064
#define NCHUNK   16
#define NTOK     (BSZ * TOTAL)         // 4128
#define MAXKEYS  144
#define ATTN_SMEM (MAXKEYS * HEAD_DIM * 2 * 4)

// ---------------------------------------------------------------------------
// Static device scratch (no cudaMalloc allowed)
// ---------------------------------------------------------------------------
__device__ __align__(1024) float g_h  [(size_t)NTOK * EMBED];
__device__ __align__(1024) float g_q  [(size_t)NTOK * EMBED];
__device__ __align__(1024) float g_k  [(size_t)NTOK * EMBED];
__device__ __align__(1024) float g_v  [(size_t)NTOK * EMBED];
__device__ __align__(1024) float g_ctx[(size_t)NTOK * EMBED];
__device__ __align__(1024) float g_x1 [(size_t)NTOK * EMBED];
__device__ __align__(1024) float g_h2 [(size_t)NTOK * EMBED];
__device__ __align__(1024) float g_mid[(size_t)NTOK * FFN_DIM];
// tf32-rounded weights
#define WR_WQ   ((size_t)0)
#define WR_WK   ((size_t)1  * 1024 * 1024)
#define WR_WV   ((size_t)2  * 1024 * 1024)
#define WR_WO   ((size_t)3  * 1024 * 1024)
#define WR_SFC1 ((size_t)4  * 1024 * 1024)
#define WR_SFC2 ((size_t)8  * 1024 * 1024)
#define WR_RFC1 ((size_t)12 * 1024 * 1024)
#define WR_RFC2 ((size_t)16 * 1024 * 1024)
__device__ __align__(1024) float g_wr[(size_t)20 * 1024 * 1024];

// ---------------------------------------------------------------------------
// PTX helpers
// ---------------------------------------------------------------------------
__device__ __forceinline__ uint32_t smem_u32(const void* p) {
    uint32_t a;
    asm("{ .reg .u64 t; cvta.to.shared.u64 t, %1; cvt.u32.u64 %0, t; }"
        : "=r"(a) : "l"(p));
    return a;
}
__device__ __forceinline__ float f2tf32(float f) {
    unsigned u;
    asm("cvt.rna.tf32.f32 %0, %1;" : "=r"(u) : "f"(f));
    return __uint_as_float(u);
}
__device__ __forceinline__ float4 cvt4(float4 v) {
    return make_float4(f2tf32(v.x), f2tf32(v.y), f2tf32(v.z), f2tf32(v.w));
}
__device__ __forceinline__ void mma_tf32(float* d, const unsigned* a, const unsigned* b) {
    asm volatile(
        "mma.sync.aligned.m16n8k8.row.col.f32.tf32.tf32.f32 "
        "{%0,%1,%2,%3}, {%4,%5,%6,%7}, {%8,%9}, {%0,%1,%2,%3};"
        : "+f"(d[0]), "+f"(d[1]), "+f"(d[2]), "+f"(d[3])
        : "r"(a[0]), "r"(a[1]), "r"(a[2]), "r"(a[3]), "r"(b[0]), "r"(b[1]));
}
__device__ __forceinline__ void ldsm_x4(unsigned* r, uint32_t addr) {
    asm volatile("ldmatrix.sync.aligned.m8n8.x4.shared.b16 {%0,%1,%2,%3}, [%4];"
                 : "=r"(r[0]), "=r"(r[1]), "=r"(r[2]), "=r"(r[3]) : "r"(addr));
}
#define CP_ASYNC16(dst, src, sz) \
    asm volatile("cp.async.cg.shared.global [%0], [%1], 16, %2;" \
                 :: "r"(dst), "l"(src), "r"(sz) : "memory")
#define CP_COMMIT() asm volatile("cp.async.commit_group;" ::: "memory")
#define CP_WAIT2()  asm volatile("cp.async.wait_group 2;" ::: "memory")

// ---------------------------------------------------------------------------
// TF32 tensor-core GEMM (NT): C[z][M,N] = op(A[z] @ B^T + bias) + resid[z]
// 128x128 tile, BK=16, 256 threads (8 warps 4x2).
// cp.async staging into XOR-swizzled smem; ldmatrix.x4 operand delivery.
// Inputs must be pre-rounded to tf32 (rna) in f32 containers.
// ---------------------------------------------------------------------------
#define STAGES 4
#define STAGE_BYTES 16384   // A 8KB + B 8KB (128 rows x 64B each)
#define GEMM_SMEM (STAGES * STAGE_BYTES)

template<bool RELU, bool HAS_BIAS, bool HAS_RESID, bool ROUND_OUT>
__global__ __launch_bounds__(256) void gemm_tc(
    const float* __restrict__ A, const float* __restrict__ B,
    float* __restrict__ C, int M, int N, int K,
    const float* __restrict__ bias, const float* __restrict__ resid,
    size_t zA, size_t zC, size_t zR)
{
    extern __shared__ char smraw[];
    const uint32_t smb = smem_u32(smraw);

    A += (size_t)blockIdx.z * zA;
    C += (size_t)blockIdx.z * zC;
    if (HAS_RESID) resid += (size_t)blockIdx.z * zR;

    const int tid  = threadIdx.x;
    const int lane = tid & 31;
    const int warp = tid >> 5;
    const int wm   = (warp >> 1) * 32;
    const int wn   = (warp & 1) * 64;

    // --- staging mapping: thread handles row tid>>1, chunks (tid&1)*2, +1 ---
    const int srow = tid >> 1;
    const int scol = (tid & 1) * 2;
    const int rowA = blockIdx.y * 128 + srow;
    const int rowB = blockIdx.x * 128 + srow;
    const uint32_t asz = (rowA < M) ? 16u : 0u;
    const float* Ag = A + (size_t)(rowA < M ? rowA : 0) * K + scol * 4;
    const float* Bg = B + (size_t)rowB * K + scol * 4;
    const uint32_t ssw   = (srow >> 1) & 3;
    const uint32_t dst0  = srow * 64 + (((uint32_t)scol ^ ssw) << 4);
    const uint32_t dst1  = srow * 64 + ((((uint32_t)scol + 1) ^ ssw) << 4);

    // --- ldmatrix lane addressing (lane-constant parts) ---
    // A atoms: rows wm + mt*16 + (lane&15), chunk base (lane>>4)
    const int arow0 = wm + (lane & 15);
    const uint32_t aoff0 = arow0 * 64,        ask0 = (arow0 >> 1) & 3;
    const uint32_t aoff1 = (arow0 + 16) * 64, ask1 = ((arow0 + 16) >> 1) & 3;
    const uint32_t acb = lane >> 4;
    // B pairs p: n = wn + p*16 + ((lane>>4)<<3) + (lane&7), chunk base (lane>>3)&1
    const int bn = wn + ((lane >> 4) << 3) + (lane & 7);
    const uint32_t bcb = (lane >> 3) & 1;
    uint32_t boff[4], bsk[4];
#pragma unroll
    for (int p = 0; p < 4; p++) {
        int n = bn + p * 16;
        boff[p] = n * 64;
        bsk[p]  = (n >> 1) & 3;
    }

    float acc[2][8][4];
#pragma unroll
    for (int mt = 0; mt < 2; mt++)
#pragma unroll
        for (int nt = 0; nt < 8; nt++)
#pragma unroll
            for (int i = 0; i < 4; i++) acc[mt][nt][i] = 0.f;

    const int nstep = K >> 4;

    // --- prologue: fill first STAGES-1 stages ---
#pragma unroll
    for (int s = 0; s < STAGES - 1; s++) {
        uint32_t ab = smb + s * STAGE_BYTES;
        uint32_t bb = ab + 8192;
        const float* ag = Ag + s * 16;
        const float* bg = Bg + s * 16;
        CP_ASYNC16(ab + dst0, ag,     asz);
        CP_ASYNC16(ab + dst1, ag + 4, asz);
        CP_ASYNC16(bb + dst0, bg,     16u);
        CP_ASYNC16(bb + dst1, bg + 4, 16u);
        CP_COMMIT();
    }

    for (int i = 0; i < nstep; i++) {
        CP_WAIT2();
        __syncthreads();

        // issue next stage (or empty group to keep accounting)
        const int nf = i + STAGES - 1;
        if (nf < nstep) {
            uint32_t ab = smb + (nf % STAGES) * STAGE_BYTES;
            uint32_t bb = ab + 8192;
            const float* ag = Ag + nf * 16;
            const float* bg = Bg + nf * 16;
            CP_ASYNC16(ab + dst0, ag,     asz);
            CP_ASYNC16(ab + dst1, ag + 4, asz);
            CP_ASYNC16(bb + dst0, bg,     16u);
            CP_ASYNC16(bb + dst1, bg + 4, 16u);
            CP_COMMIT();
        } else {
            CP_COMMIT();
        }

        const uint32_t ab = smb + (i % STAGES) * STAGE_BYTES;
        const uint32_t bb = ab + 8192;

#pragma unroll
        for (int sub = 0; sub < 2; sub++) {
            const uint32_t ch = sub * 2 + acb;
            unsigned a0[4], a1[4], b[4][4];
            ldsm_x4(a0, ab + aoff0 + (((ch ^ ask0)) << 4));
            ldsm_x4(a1, ab + aoff1 + (((ch ^ ask1)) << 4));
            const uint32_t chb = sub * 2 + bcb;
#pragma unroll
            for (int p = 0; p < 4; p++)
                ldsm_x4(b[p], bb + boff[p] + (((chb ^ bsk[p])) << 4));
#pragma unroll
            for (int p = 0; p < 4; p++) {
                mma_tf32(acc[0][2 * p    ], a0, &b[p][0]);
                mma_tf32(acc[0][2 * p + 1], a0, &b[p][2]);
                mma_tf32(acc[1][2 * p    ], a1, &b[p][0]);
                mma_tf32(acc[1][2 * p + 1], a1, &b[p][2]);
            }
        }
        __syncthreads();
    }

    // --- epilogue (R4 layout: fr = lane>>2, fk = lane&3) ---
    const int fr = lane >> 2, fk = lane & 3;
    const int rowbase = blockIdx.y * 128 + wm + fr;
    const int colbase = blockIdx.x * 128 + wn + fk * 2;
#pragma unroll
    for (int mt = 0; mt < 2; mt++) {
#pragma unroll
        for (int half = 0; half < 2; half++) {
            int r = rowbase + mt * 16 + half * 8;
            if (r >= M) continue;
#pragma unroll
            for (int nt = 0; nt < 8; nt++) {
                int cidx = colbase + nt * 8;
                float v0 = acc[mt][nt][half * 2 + 0];
                float v1 = acc[mt][nt][half * 2 + 1];
                if (HAS_BIAS) { v0 += bias[cidx]; v1 += bias[cidx + 1]; }
                if (RELU) { v0 = fmaxf(v0, 0.f); v1 = fmaxf(v1, 0.f); }
                if (HAS_RESID) {
                    float2 rr = *(const float2*)(resid + (size_t)r * N + cidx);
                    v0 += rr.x; v1 += rr.y;
                }
                if (ROUND_OUT) { v0 = f2tf32(v0); v1 = f2tf32(v1); }
                *(float2*)(C + (size_t)r * N + cidx) = make_float2(v0, v1);
            }
        }
    }
}

// ---------------------------------------------------------------------------
// Weight rounding f32 -> tf32(rna)
// ---------------------------------------------------------------------------
__global__ __launch_bounds__(256) void round_tf32_kernel(
    const float4* __restrict__ in, float4* __restrict__ out, int n4)
{
    int i = blockIdx.x * 256 + threadIdx.x;
    if (i < n4) out[i] = cvt4(in[i]);
}

// ---------------------------------------------------------------------------
// LayerNorm (output rounded to tf32 — consumed only as GEMM A operand)
// ---------------------------------------------------------------------------
__global__ __launch_bounds__(256) void ln_kernel(
    const float* __restrict__ x,
    const float* __restrict__ gs, const float* __restrict__ bs,
    const float* __restrict__ gr, const float* __restrict__ br,
    float* __restrict__ out)
{
    int row = blockIdx.x;
    int t = row % TOTAL;
    const float* g = (t < SUM_LEN) ? gs : gr;
    const float* b = (t < SUM_LEN) ? bs : br;
    int tid = threadIdx.x;
    int lane = tid & 31, warp = tid >> 5;

    float4 v = ((const float4*)(x + (size_t)row * EMBED))[tid];
    float s = v.x + v.y + v.z + v.w;
    float q = v.x * v.x + v.y * v.y + v.z * v.z + v.w * v.w;

    __shared__ float rs_[8], rq_[8];
#pragma unroll
    for (int o = 16; o; o >>= 1) {
        s += __shfl_xor_sync(0xffffffffu, s, o);
        q += __shfl_xor_sync(0xffffffffu, q, o);
    }
    if (lane == 0) { rs_[warp] = s; rq_[warp] = q; }
    __syncthreads();
    if (tid < 32) {
        s = (lane < 8) ? rs_[lane] : 0.f;
        q = (lane < 8) ? rq_[lane] : 0.f;
#pragma unroll
        for (int o = 4; o; o >>= 1) {
            s += __shfl_xor_sync(0xffffffffu, s, o);
            q += __shfl_xor_sync(0xffffffffu, q, o);
        }
        if (lane == 0) { rs_[0] = s; rq_[0] = q; }
    }
    __syncthreads();

    float mean = rs_[0] * (1.f / EMBED);
    float var  = rq_[0] * (1.f / EMBED) - mean * mean;
    float rinv = rsqrtf(var + 1e-5f);

    float4 gg = ((const float4*)g)[tid];
    float4 bb = ((const float4*)b)[tid];
    float4 o4;
    o4.x = (v.x - mean) * rinv * gg.x + bb.x;
    o4.y = (v.y - mean) * rinv * gg.y + bb.y;
    o4.z = (v.z - mean) * rinv * gg.z + bb.z;
    o4.w = (v.w - mean) * rinv * gg.w + bb.w;
    ((float4*)(out + (size_t)row * EMBED))[tid] = cvt4(o4);
}

// ---------------------------------------------------------------------------
// Attention, REG queries. Grid (NCHUNK, HEADS, BSZ), 256 threads.
// Thread PAIR per query: thread owns 32 of 64 head dims; dot via shfl.
// ---------------------------------------------------------------------------
__global__ __launch_bounds__(256) void attn_reg_kernel(
    const float* __restrict__ Q, const float* __restrict__ K,
    const float* __restrict__ V, const int* __restrict__ ranges,
    float* __restrict__ CTX)
{
    extern __shared__ float sm[];
    float* Ks = sm;
    float* Vs = sm + MAXKEYS * HEAD_DIM;

    int c = blockIdx.x, h = blockIdx.y, b = blockIdx.z;
    int start = ranges[(b * NCHUNK + c) * 2];
    int next  = (c + 1 < NCHUNK) ? ranges[(b * NCHUNK + c + 1) * 2] : REG_LEN;
    int width = next - start;     // 128 in this dataset
    int nsum  = c;
    int nk    = nsum + width;

    for (int idx = threadIdx.x; idx < nk * 16; idx += 256) {
        int j = idx >> 4, f = idx & 15;
        int tok = (j < nsum) ? j : (SUM_LEN + start + (j - nsum));
        size_t off = ((size_t)b * TOTAL + tok) * EMBED + h * HEAD_DIM;
        ((float4*)Ks)[j * 16 + f] = ((const float4*)(K + off))[f];
        ((float4*)Vs)[j * 16 + f] = ((const float4*)(V + off))[f];
    }
    __syncthreads();

    const int qi   = threadIdx.x >> 1;
    const int half = threadIdx.x & 1;
    const unsigned pmask = 3u << ((threadIdx.x & 31) & ~1);

    if (qi < width) {
        int tq = SUM_LEN + start + qi;
        const float4* qp = (const float4*)(Q + ((size_t)b * TOTAL + tq) * EMBED
                                           + h * HEAD_DIM + half * 32);
        float qreg[32];
#pragma unroll
        for (int f = 0; f < 8; f++) {
            float4 t4 = qp[f];
            qreg[4 * f + 0] = t4.x * 0.125f;
            qreg[4 * f + 1] = t4.y * 0.125f;
            qreg[4 * f + 2] = t4.z * 0.125f;
            qreg[4 * f + 3] = t4.w * 0.125f;
        }
        float m = -1e30f, l = 0.f;
        float ctx[32];
#pragma unroll
        for (int d = 0; d < 32; d++) ctx[d] = 0.f;

        const int jmax = nsum + qi + 1;
        for (int j = 0; j < jmax; j++) {
            const float4* kj = (const float4*)(Ks + j * HEAD_DIM + half * 32);
            float s0 = 0.f, s1 = 0.f, s2 = 0.f, s3 = 0.f;
#pragma unroll
            for (int f = 0; f < 8; f++) {
                float4 kk = kj[f];
                s0 = fmaf(qreg[4 * f + 0], kk.x, s0);
                s1 = fmaf(qreg[4 * f + 1], kk.y, s1);
                s2 = fmaf(qreg[4 * f + 2], kk.z, s2);
                s3 = fmaf(qreg[4 * f + 3], kk.w, s3);
            }
            float sd = (s0 + s1) + (s2 + s3);
            sd += __shfl_xor_sync(pmask, sd, 1);
            float mn = fmaxf(m, sd);
            float alpha = __expf(m - mn);
            float p = __expf(sd - mn);
            l = l * alpha + p;
            const float4* vj = (const float4*)(Vs + j * HEAD_DIM + half * 32);
#pragma unroll
            for (int f = 0; f < 8; f++) {
                float4 vv = vj[f];
                ctx[4 * f + 0] = fmaf(p, vv.x, ctx[4 * f + 0] * alpha);
                ctx[4 * f + 1] = fmaf(p, vv.y, ctx[4 * f + 1] * alpha);
                ctx[4 * f + 2] = fmaf(p, vv.z, ctx[4 * f + 2] * alpha);
                ctx[4 * f + 3] = fmaf(p, vv.w, ctx[4 * f + 3] * alpha);
            }
            m = mn;
        }
        float inv = 1.f / l;
        float4* op = (float4*)(CTX + ((size_t)b * TOTAL + tq) * EMBED
                               + h * HEAD_DIM + half * 32);
#pragma unroll
        for (int f = 0; f < 8; f++)
            op[f] = cvt4(make_float4(ctx[4 * f + 0] * inv, ctx[4 * f + 1] * inv,
                                     ctx[4 * f + 2] * inv, ctx[4 * f + 3] * inv));
    }
}

// ---------------------------------------------------------------------------
// Attention, SUM queries. One warp per (b, h, s); output rounded.
// ---------------------------------------------------------------------------
__global__ __launch_bounds__(256) void attn_sum_kernel(
    const float* __restrict__ Q, const float* __restrict__ K,
    const float* __restrict__ V, const int* __restrict__ ranges,
    float* __restrict__ CTX)
{
    int gw = (blockIdx.x * blockDim.x + threadIdx.x) >> 5;
    int lane = threadIdx.x & 31;
    if (gw >= BSZ * HEADS * SUM_LEN) return;
    int b = gw / (HEADS * SUM_LEN);
    int rem = gw % (HEADS * SUM_LEN);
    int h = rem / SUM_LEN;
    int s = rem % SUM_LEN;

    int start = ranges[(b * NCHUNK + s) * 2];
    int next  = (s + 1 < NCHUNK) ? ranges[(b * NCHUNK + s + 1) * 2] : REG_LEN;

    size_t bbase = (size_t)b * TOTAL;
    float2 q2 = ((const float2*)(Q + (bbase + s) * EMBED + h * HEAD_DIM))[lane];
    q2.x *= 0.125f; q2.y *= 0.125f;

    float m = -1e30f, l = 0.f, cx = 0.f, cy = 0.f;

#define ASTEP(tok_expr)                                                                \
    do {                                                                               \
        int tok = (tok_expr);                                                          \
        float2 kk = ((const float2*)(K + (bbase + tok) * EMBED + h * HEAD_DIM))[lane]; \
        float part = q2.x * kk.x + q2.y * kk.y;                                        \
        _Pragma("unroll")                                                              \
        for (int o = 16; o; o >>= 1) part += __shfl_xor_sync(0xffffffffu, part, o);    \
        float mn = fmaxf(m, part);                                                     \
        float alpha = __expf(m - mn);                                                  \
        float p = __expf(part - mn);                                                   \
        l = l * alpha + p;                                                             \
        float2 vv = ((const float2*)(V + (bbase + tok) * EMBED + h * HEAD_DIM))[lane]; \
        cx = fmaf(p, vv.x, cx * alpha);                                                \
        cy = fmaf(p, vv.y, cy * alpha);                                                \
        m = mn;                                                                        \
    } while (0)

    for (int t = 0; t <= s; t++)       ASTEP(t);
    for (int t = start; t < next; t++) ASTEP(SUM_LEN + t);
#undef ASTEP

    float inv = 1.f / l;
    ((float2*)(CTX + (bbase + s) * EMBED + h * HEAD_DIM))[lane] =
        make_float2(f2tf32(cx * inv), f2tf32(cy * inv));
}

// ---------------------------------------------------------------------------
// Launch sequence
// ---------------------------------------------------------------------------
extern "C" void kernel_launch(void* const* d_in, const int* in_sizes, int n_in,
                              void* d_out, int out_size)
{
    const float* x      = (const float*)d_in[0];
    const float* w_q    = (const float*)d_in[1];
    const float* w_k    = (const float*)d_in[2];
    const float* w_v    = (const float*)d_in[3];
    const float* w_o    = (const float*)d_in[4];
    const float* ln1_sg = (const float*)d_in[5];
    const float* ln1_sb = (const float*)d_in[6];
    const float* ln1_rg = (const float*)d_in[7];
    const float* ln1_rb = (const float*)d_in[8];
    const float* sfc1w  = (const float*)d_in[9];
    const float* sfc1b  = (const float*)d_in[10];
    const float* sfc2w  = (const float*)d_in[11];
    const float* sfc2b  = (const float*)d_in[12];
    const float* rfc1w  = (const float*)d_in[13];
    const float* rfc1b  = (const float*)d_in[14];
    const float* rfc2w  = (const float*)d_in[15];
    const float* rfc2b  = (const float*)d_in[16];
    const float* ln2_sg = (const float*)d_in[17];
    const float* ln2_sb = (const float*)d_in[18];
    const float* ln2_rg = (const float*)d_in[19];
    const float* ln2_rb = (const float*)d_in[20];
    const int*   ranges = (const int*)d_in[21];
    float* out = (float*)d_out;

    void *ph, *pq, *pk, *pv, *pctx, *px1, *ph2, *pmid, *pwr;
    cudaGetSymbolAddress(&ph,   g_h);
    cudaGetSymbolAddress(&pq,   g_q);
    cudaGetSymbolAddress(&pk,   g_k);
    cudaGetSymbolAddress(&pv,   g_v);
    cudaGetSymbolAddress(&pctx, g_ctx);
    cudaGetSymbolAddress(&px1,  g_x1);
    cudaGetSymbolAddress(&ph2,  g_h2);
    cudaGetSymbolAddress(&pmid, g_mid);
    cudaGetSymbolAddress(&pwr,  g_wr);
    float* h   = (float*)ph;
    float* q   = (float*)pq;
    float* k   = (float*)pk;
    float* v   = (float*)pv;
    float* ctx = (float*)pctx;
    float* x1  = (float*)px1;
    float* h2  = (float*)ph2;
    float* mid = (float*)pmid;
    float* wr  = (float*)pwr;

    const size_t zE = (size_t)TOTAL * EMBED;
    const size_t zF = (size_t)TOTAL * FFN_DIM;

    cudaFuncSetAttribute(attn_reg_kernel,
                         cudaFuncAttributeMaxDynamicSharedMemorySize, ATTN_SMEM);
    cudaFuncSetAttribute(gemm_tc<false, false, false, false>,
                         cudaFuncAttributeMaxDynamicSharedMemorySize, GEMM_SMEM);
    cudaFuncSetAttribute(gemm_tc<false, false, true, false>,
                         cudaFuncAttributeMaxDynamicSharedMemorySize, GEMM_SMEM);
    cudaFuncSetAttribute(gemm_tc<true, true, false, true>,
                         cudaFuncAttributeMaxDynamicSharedMemorySize, GEMM_SMEM);
    cudaFuncSetAttribute(gemm_tc<false, true, true, false>,
                         cudaFuncAttributeMaxDynamicSharedMemorySize, GEMM_SMEM);

    // 0) Round weights to tf32 (rna)
    {
        int n1 = (1024 * 1024) / 4, n4 = (4096 * 1024) / 4;
        round_tf32_kernel<<<(n1 + 255) / 256, 256>>>((const float4*)w_q,   (float4*)(wr + WR_WQ),   n1);
        round_tf32_kernel<<<(n1 + 255) / 256, 256>>>((const float4*)w_k,   (float4*)(wr + WR_WK),   n1);
        round_tf32_kernel<<<(n1 + 255) / 256, 256>>>((const float4*)w_v,   (float4*)(wr + WR_WV),   n1);
        round_tf32_kernel<<<(n1 + 255) / 256, 256>>>((const float4*)w_o,   (float4*)(wr + WR_WO),   n1);
        round_tf32_kernel<<<(n4 + 255) / 256, 256>>>((const float4*)sfc1w, (float4*)(wr + WR_SFC1), n4);
        round_tf32_kernel<<<(n4 + 255) / 256, 256>>>((const float4*)sfc2w, (float4*)(wr + WR_SFC2), n4);
        round_tf32_kernel<<<(n4 + 255) / 256, 256>>>((const float4*)rfc1w, (float4*)(wr + WR_RFC1), n4);
        round_tf32_kernel<<<(n4 + 255) / 256, 256>>>((const float4*)rfc2w, (float4*)(wr + WR_RFC2), n4);
    }

    // 1) LN1 (tf32-rounded output)
    ln_kernel<<<NTOK, 256>>>(x, ln1_sg, ln1_sb, ln1_rg, ln1_rb, h);

    // 2) QKV projections: M=4128, N=1024, K=1024
    dim3 gP(8, 33, 1);
    gemm_tc<false, false, false, false><<<gP, 256, GEMM_SMEM>>>(
        h, wr + WR_WQ, q, NTOK, EMBED, EMBED, nullptr, nullptr, 0, 0, 0);
    gemm_tc<false, false, false, false><<<gP, 256, GEMM_SMEM>>>(
        h, wr + WR_WK, k, NTOK, EMBED, EMBED, nullptr, nullptr, 0, 0, 0);
    gemm_tc<false, false, false, false><<<gP, 256, GEMM_SMEM>>>(
        h, wr + WR_WV, v, NTOK, EMBED, EMBED, nullptr, nullptr, 0, 0, 0);

    // 3) Sparse masked attention (ctx rounded to tf32)
    attn_reg_kernel<<<dim3(NCHUNK, HEADS, BSZ), 256, ATTN_SMEM>>>(q, k, v, ranges, ctx);
    attn_sum_kernel<<<(BSZ * HEADS * SUM_LEN) / 8, 256>>>(q, k, v, ranges, ctx);

    // 4) Output projection + residual: x1 = x + ctx @ Wo^T
    gemm_tc<false, false, true, false><<<gP, 256, GEMM_SMEM>>>(
        ctx, wr + WR_WO, x1, NTOK, EMBED, EMBED, nullptr, x, 0, 0, 0);

    // 5) LN2 (rounded)
    ln_kernel<<<NTOK, 256>>>(x1, ln2_sg, ln2_sb, ln2_rg, ln2_rb, h2);

    // 6) FFN — reg segments (M=2048, batched z=2)
    gemm_tc<true, true, false, true><<<dim3(32, 16, BSZ), 256, GEMM_SMEM>>>(
        h2 + (size_t)SUM_LEN * EMBED, wr + WR_RFC1, mid + (size_t)SUM_LEN * FFN_DIM,
        REG_LEN, FFN_DIM, EMBED, rfc1b, nullptr, zE, zF, 0);
    gemm_tc<false, true, true, false><<<dim3(8, 16, BSZ), 256, GEMM_SMEM>>>(
        mid + (size_t)SUM_LEN * FFN_DIM, wr + WR_RFC2, out + (size_t)SUM_LEN * EMBED,
        REG_LEN, EMBED, FFN_DIM, rfc2b, x1 + (size_t)SUM_LEN * EMBED, zF, zE, zE);

    //    sum segments (M=16, batched z=2)
    gemm_tc<true, true, false, true><<<dim3(32, 1, BSZ), 256, GEMM_SMEM>>>(
        h2, wr + WR_SFC1, mid, SUM_LEN, FFN_DIM, EMBED, sfc1b, nullptr, zE, zF, 0);
    gemm_tc<false, true, true, false><<<dim3(8, 1, BSZ), 256, GEMM_SMEM>>>(
        mid, wr + WR_SFC2, out, SUM_LEN, EMBED, FFN_DIM, sfc2b, x1, zF, zE, zE);
}

// round 9
// speedup vs baseline: 4.3593x; 1.0530x over previous
#include <cuda_runtime.h>
#include <cstdint>
#include <cstddef>

// ---------------------------------------------------------------------------
#define EMBED    1024
#define HEADS    16
#define HEAD_DIM 64
#define FFN_DIM  4096
#define BSZ      2
#define SUM_LEN  16
#define REG_LEN  2048
#define TOTAL    (SUM_LEN + REG_LEN)   // 2064
#define NCHUNK   16
#define NTOK     (BSZ * TOTAL)         // 4128
#define MAXKEYS  144
#define ATTN_SMEM (MAXKEYS * HEAD_DIM * 2 * 4)
#define QKV_STR  3072                  // fused qkv row stride

// ---------------------------------------------------------------------------
// Static device scratch (no cudaMalloc allowed)
// ---------------------------------------------------------------------------
__device__ __align__(1024) float g_h  [(size_t)NTOK * EMBED];
__device__ __align__(1024) float g_ctx[(size_t)NTOK * EMBED];
__device__ __align__(1024) float g_x1 [(size_t)NTOK * EMBED];
__device__ __align__(1024) float g_h2 [(size_t)NTOK * EMBED];
__device__ __align__(1024) float g_mid[(size_t)NTOK * FFN_DIM];  // qkv, then ffn mid
// tf32-rounded weights (contiguous; wq|wk|wv contiguous => fused qkv B matrix)
#define WR_WQ   ((size_t)0)
#define WR_WK   ((size_t)1  * 1024 * 1024)
#define WR_WV   ((size_t)2  * 1024 * 1024)
#define WR_WO   ((size_t)3  * 1024 * 1024)
#define WR_SFC1 ((size_t)4  * 1024 * 1024)
#define WR_SFC2 ((size_t)8  * 1024 * 1024)
#define WR_RFC1 ((size_t)12 * 1024 * 1024)
#define WR_RFC2 ((size_t)16 * 1024 * 1024)
__device__ __align__(1024) float g_wr[(size_t)20 * 1024 * 1024];

// ---------------------------------------------------------------------------
// PTX helpers
// ---------------------------------------------------------------------------
__device__ __forceinline__ uint32_t smem_u32(const void* p) {
    uint32_t a;
    asm("{ .reg .u64 t; cvta.to.shared.u64 t, %1; cvt.u32.u64 %0, t; }"
        : "=r"(a) : "l"(p));
    return a;
}
__device__ __forceinline__ float f2tf32(float f) {
    unsigned u;
    asm("cvt.rna.tf32.f32 %0, %1;" : "=r"(u) : "f"(f));
    return __uint_as_float(u);
}
__device__ __forceinline__ float4 cvt4(float4 v) {
    return make_float4(f2tf32(v.x), f2tf32(v.y), f2tf32(v.z), f2tf32(v.w));
}
__device__ __forceinline__ void mma_tf32(float* d, const unsigned* a, const unsigned* b) {
    asm volatile(
        "mma.sync.aligned.m16n8k8.row.col.f32.tf32.tf32.f32 "
        "{%0,%1,%2,%3}, {%4,%5,%6,%7}, {%8,%9}, {%0,%1,%2,%3};"
        : "+f"(d[0]), "+f"(d[1]), "+f"(d[2]), "+f"(d[3])
        : "r"(a[0]), "r"(a[1]), "r"(a[2]), "r"(a[3]), "r"(b[0]), "r"(b[1]));
}
__device__ __forceinline__ void ldsm_x4(unsigned* r, uint32_t addr) {
    asm volatile("ldmatrix.sync.aligned.m8n8.x4.shared.b16 {%0,%1,%2,%3}, [%4];"
                 : "=r"(r[0]), "=r"(r[1]), "=r"(r[2]), "=r"(r[3]) : "r"(addr));
}
#define CP_ASYNC16(dst, src, sz) \
    asm volatile("cp.async.cg.shared.global [%0], [%1], 16, %2;" \
                 :: "r"(dst), "l"(src), "r"(sz) : "memory")
#define CP_COMMIT() asm volatile("cp.async.commit_group;" ::: "memory")
#define CP_WAIT2()  asm volatile("cp.async.wait_group 2;" ::: "memory")

// ---------------------------------------------------------------------------
// TF32 tensor-core GEMM (NT): C[z][M,N] = op(A[z] @ B^T + bias) + resid[z]
// 128x128 tile, BK=16, 256 threads (8 warps 4x2).
// cp.async (4-stage, ONE barrier per k-iter) + XOR-swizzled smem + ldmatrix.x4.
// Inputs must be pre-rounded to tf32 (rna) in f32 containers.
// NC = C/resid row stride (N columns written at blockIdx.x*128 within it).
// ---------------------------------------------------------------------------
#define STAGES 4
#define STAGE_BYTES 16384   // A 8KB + B 8KB (128 rows x 64B each)
#define GEMM_SMEM (STAGES * STAGE_BYTES)

template<bool RELU, bool HAS_BIAS, bool HAS_RESID, bool ROUND_OUT>
__global__ __launch_bounds__(256) void gemm_tc(
    const float* __restrict__ A, const float* __restrict__ B,
    float* __restrict__ C, int M, int NC, int K,
    const float* __restrict__ bias, const float* __restrict__ resid,
    size_t zA, size_t zC, size_t zR)
{
    extern __shared__ char smraw[];
    const uint32_t smb = smem_u32(smraw);

    A += (size_t)blockIdx.z * zA;
    C += (size_t)blockIdx.z * zC;
    if (HAS_RESID) resid += (size_t)blockIdx.z * zR;

    const int tid  = threadIdx.x;
    const int lane = tid & 31;
    const int warp = tid >> 5;
    const int wm   = (warp >> 1) * 32;
    const int wn   = (warp & 1) * 64;

    // staging: thread owns row tid>>1, k-chunks (tid&1)*2 and +1
    const int srow = tid >> 1;
    const int scol = (tid & 1) * 2;
    const int rowA = blockIdx.y * 128 + srow;
    const int rowB = blockIdx.x * 128 + srow;
    const uint32_t asz = (rowA < M) ? 16u : 0u;
    const float* Ag = A + (size_t)(rowA < M ? rowA : 0) * K + scol * 4;
    const float* Bg = B + (size_t)rowB * K + scol * 4;
    const uint32_t ssw  = (srow >> 1) & 3;
    const uint32_t dst0 = srow * 64 + (((uint32_t)scol ^ ssw) << 4);
    const uint32_t dst1 = srow * 64 + ((((uint32_t)scol + 1) ^ ssw) << 4);

    // ldmatrix lane addressing
    const int arow0 = wm + (lane & 15);
    const uint32_t aoff0 = arow0 * 64,        ask0 = (arow0 >> 1) & 3;
    const uint32_t aoff1 = (arow0 + 16) * 64, ask1 = ((arow0 + 16) >> 1) & 3;
    const uint32_t acb = lane >> 4;
    const int bn = wn + ((lane >> 4) << 3) + (lane & 7);
    const uint32_t bcb = (lane >> 3) & 1;
    uint32_t boff[4], bsk[4];
#pragma unroll
    for (int p = 0; p < 4; p++) {
        int n = bn + p * 16;
        boff[p] = n * 64;
        bsk[p]  = (n >> 1) & 3;
    }

    float acc[2][8][4];
#pragma unroll
    for (int mt = 0; mt < 2; mt++)
#pragma unroll
        for (int nt = 0; nt < 8; nt++)
#pragma unroll
            for (int i = 0; i < 4; i++) acc[mt][nt][i] = 0.f;

    const int nstep = K >> 4;

    // prologue: stages 0..2
#pragma unroll
    for (int s = 0; s < STAGES - 1; s++) {
        uint32_t ab = smb + s * STAGE_BYTES;
        uint32_t bb = ab + 8192;
        const float* ag = Ag + s * 16;
        const float* bg = Bg + s * 16;
        CP_ASYNC16(ab + dst0, ag,     asz);
        CP_ASYNC16(ab + dst1, ag + 4, asz);
        CP_ASYNC16(bb + dst0, bg,     16u);
        CP_ASYNC16(bb + dst1, bg + 4, 16u);
        CP_COMMIT();
    }

    for (int i = 0; i < nstep; i++) {
        CP_WAIT2();           // stage i%STAGES complete
        __syncthreads();      // ALL warps past iter i-1 reads -> safe to refill

        const int nf = i + STAGES - 1;
        if (nf < nstep) {     // refill stage (i+3)%4 == (i-1)%4 (read at iter i-1)
            uint32_t ab = smb + (nf % STAGES) * STAGE_BYTES;
            uint32_t bb = ab + 8192;
            const float* ag = Ag + nf * 16;
            const float* bg = Bg + nf * 16;
            CP_ASYNC16(ab + dst0, ag,     asz);
            CP_ASYNC16(ab + dst1, ag + 4, asz);
            CP_ASYNC16(bb + dst0, bg,     16u);
            CP_ASYNC16(bb + dst1, bg + 4, 16u);
        }
        CP_COMMIT();          // unconditional: keeps group accounting aligned

        const uint32_t ab = smb + (i % STAGES) * STAGE_BYTES;
        const uint32_t bb = ab + 8192;

#pragma unroll
        for (int sub = 0; sub < 2; sub++) {
            const uint32_t ch = sub * 2 + acb;
            unsigned a0[4], a1[4], b[4][4];
            ldsm_x4(a0, ab + aoff0 + ((ch ^ ask0) << 4));
            ldsm_x4(a1, ab + aoff1 + ((ch ^ ask1) << 4));
            const uint32_t chb = sub * 2 + bcb;
#pragma unroll
            for (int p = 0; p < 4; p++)
                ldsm_x4(b[p], bb + boff[p] + ((chb ^ bsk[p]) << 4));
#pragma unroll
            for (int p = 0; p < 4; p++) {
                mma_tf32(acc[0][2 * p    ], a0, &b[p][0]);
                mma_tf32(acc[0][2 * p + 1], a0, &b[p][2]);
                mma_tf32(acc[1][2 * p    ], a1, &b[p][0]);
                mma_tf32(acc[1][2 * p + 1], a1, &b[p][2]);
            }
        }
    }

    // epilogue
    const int fr = lane >> 2, fk = lane & 3;
    const int rowbase = blockIdx.y * 128 + wm + fr;
    const int colbase = blockIdx.x * 128 + wn + fk * 2;
#pragma unroll
    for (int mt = 0; mt < 2; mt++) {
#pragma unroll
        for (int half = 0; half < 2; half++) {
            int r = rowbase + mt * 16 + half * 8;
            if (r >= M) continue;
#pragma unroll
            for (int nt = 0; nt < 8; nt++) {
                int cidx = colbase + nt * 8;
                float v0 = acc[mt][nt][half * 2 + 0];
                float v1 = acc[mt][nt][half * 2 + 1];
                if (HAS_BIAS) { v0 += bias[cidx]; v1 += bias[cidx + 1]; }
                if (RELU) { v0 = fmaxf(v0, 0.f); v1 = fmaxf(v1, 0.f); }
                if (HAS_RESID) {
                    float2 rr = *(const float2*)(resid + (size_t)r * NC + cidx);
                    v0 += rr.x; v1 += rr.y;
                }
                if (ROUND_OUT) { v0 = f2tf32(v0); v1 = f2tf32(v1); }
                *(float2*)(C + (size_t)r * NC + cidx) = make_float2(v0, v1);
            }
        }
    }
}

// ---------------------------------------------------------------------------
// Fused weight rounding: ONE launch rounds all 8 weight matrices into g_wr.
// Layout (float4 units): 4 x 256K (wq,wk,wv,wo) then 4 x 1M (sfc1,sfc2,rfc1,rfc2)
// ---------------------------------------------------------------------------
struct RoundSrcs { const float4* s[8]; };

__global__ __launch_bounds__(256) void round_all_kernel(
    RoundSrcs srcs, float4* __restrict__ dst)
{
    size_t i = (size_t)blockIdx.x * 256 + threadIdx.x;   // < 5242880
    int r; size_t base;
    if (i < 1048576) { r = (int)(i >> 18);       base = (size_t)r << 18; }
    else             { r = 3 + (int)(i >> 20);   base = (size_t)(r - 3) << 20; }
    dst[i] = cvt4(srcs.s[r][i - base]);
}

// ---------------------------------------------------------------------------
// LayerNorm (output rounded to tf32 — consumed only as GEMM A operand)
// ---------------------------------------------------------------------------
__global__ __launch_bounds__(256) void ln_kernel(
    const float* __restrict__ x,
    const float* __restrict__ gs, const float* __restrict__ bs,
    const float* __restrict__ gr, const float* __restrict__ br,
    float* __restrict__ out)
{
    int row = blockIdx.x;
    int t = row % TOTAL;
    const float* g = (t < SUM_LEN) ? gs : gr;
    const float* b = (t < SUM_LEN) ? bs : br;
    int tid = threadIdx.x;
    int lane = tid & 31, warp = tid >> 5;

    float4 v = ((const float4*)(x + (size_t)row * EMBED))[tid];
    float s = v.x + v.y + v.z + v.w;
    float q = v.x * v.x + v.y * v.y + v.z * v.z + v.w * v.w;

    __shared__ float rs_[8], rq_[8];
#pragma unroll
    for (int o = 16; o; o >>= 1) {
        s += __shfl_xor_sync(0xffffffffu, s, o);
        q += __shfl_xor_sync(0xffffffffu, q, o);
    }
    if (lane == 0) { rs_[warp] = s; rq_[warp] = q; }
    __syncthreads();
    if (tid < 32) {
        s = (lane < 8) ? rs_[lane] : 0.f;
        q = (lane < 8) ? rq_[lane] : 0.f;
#pragma unroll
        for (int o = 4; o; o >>= 1) {
            s += __shfl_xor_sync(0xffffffffu, s, o);
            q += __shfl_xor_sync(0xffffffffu, q, o);
        }
        if (lane == 0) { rs_[0] = s; rq_[0] = q; }
    }
    __syncthreads();

    float mean = rs_[0] * (1.f / EMBED);
    float var  = rq_[0] * (1.f / EMBED) - mean * mean;
    float rinv = rsqrtf(var + 1e-5f);

    float4 gg = ((const float4*)g)[tid];
    float4 bb = ((const float4*)b)[tid];
    float4 o4;
    o4.x = (v.x - mean) * rinv * gg.x + bb.x;
    o4.y = (v.y - mean) * rinv * gg.y + bb.y;
    o4.z = (v.z - mean) * rinv * gg.z + bb.z;
    o4.w = (v.w - mean) * rinv * gg.w + bb.w;
    ((float4*)(out + (size_t)row * EMBED))[tid] = cvt4(o4);
}

// ---------------------------------------------------------------------------
// Attention, REG queries. QKV fused buffer (row stride QKV_STR).
// Grid (NCHUNK, HEADS, BSZ), 256 threads; thread PAIR per query.
// ---------------------------------------------------------------------------
__global__ __launch_bounds__(256) void attn_reg_kernel(
    const float* __restrict__ QKV, const int* __restrict__ ranges,
    float* __restrict__ CTX)
{
    extern __shared__ float sm[];
    float* Ks = sm;
    float* Vs = sm + MAXKEYS * HEAD_DIM;

    int c = blockIdx.x, h = blockIdx.y, b = blockIdx.z;
    int start = ranges[(b * NCHUNK + c) * 2];
    int next  = (c + 1 < NCHUNK) ? ranges[(b * NCHUNK + c + 1) * 2] : REG_LEN;
    int width = next - start;
    int nsum  = c;
    int nk    = nsum + width;

    for (int idx = threadIdx.x; idx < nk * 16; idx += 256) {
        int j = idx >> 4, f = idx & 15;
        int tok = (j < nsum) ? j : (SUM_LEN + start + (j - nsum));
        size_t off = ((size_t)b * TOTAL + tok) * QKV_STR + h * HEAD_DIM;
        ((float4*)Ks)[j * 16 + f] = ((const float4*)(QKV + off + 1024))[f];
        ((float4*)Vs)[j * 16 + f] = ((const float4*)(QKV + off + 2048))[f];
    }
    __syncthreads();

    const int qi   = threadIdx.x >> 1;
    const int half = threadIdx.x & 1;
    const unsigned pmask = 3u << ((threadIdx.x & 31) & ~1);

    if (qi < width) {
        int tq = SUM_LEN + start + qi;
        const float4* qp = (const float4*)(QKV + ((size_t)b * TOTAL + tq) * QKV_STR
                                           + h * HEAD_DIM + half * 32);
        float qreg[32];
#pragma unroll
        for (int f = 0; f < 8; f++) {
            float4 t4 = qp[f];
            qreg[4 * f + 0] = t4.x * 0.125f;
            qreg[4 * f + 1] = t4.y * 0.125f;
            qreg[4 * f + 2] = t4.z * 0.125f;
            qreg[4 * f + 3] = t4.w * 0.125f;
        }
        float m = -1e30f, l = 0.f;
        float ctx[32];
#pragma unroll
        for (int d = 0; d < 32; d++) ctx[d] = 0.f;

        const int jmax = nsum + qi + 1;
        for (int j = 0; j < jmax; j++) {
            const float4* kj = (const float4*)(Ks + j * HEAD_DIM + half * 32);
            float s0 = 0.f, s1 = 0.f, s2 = 0.f, s3 = 0.f;
#pragma unroll
            for (int f = 0; f < 8; f++) {
                float4 kk = kj[f];
                s0 = fmaf(qreg[4 * f + 0], kk.x, s0);
                s1 = fmaf(qreg[4 * f + 1], kk.y, s1);
                s2 = fmaf(qreg[4 * f + 2], kk.z, s2);
                s3 = fmaf(qreg[4 * f + 3], kk.w, s3);
            }
            float sd = (s0 + s1) + (s2 + s3);
            sd += __shfl_xor_sync(pmask, sd, 1);
            float mn = fmaxf(m, sd);
            float alpha = __expf(m - mn);
            float p = __expf(sd - mn);
            l = l * alpha + p;
            const float4* vj = (const float4*)(Vs + j * HEAD_DIM + half * 32);
#pragma unroll
            for (int f = 0; f < 8; f++) {
                float4 vv = vj[f];
                ctx[4 * f + 0] = fmaf(p, vv.x, ctx[4 * f + 0] * alpha);
                ctx[4 * f + 1] = fmaf(p, vv.y, ctx[4 * f + 1] * alpha);
                ctx[4 * f + 2] = fmaf(p, vv.z, ctx[4 * f + 2] * alpha);
                ctx[4 * f + 3] = fmaf(p, vv.w, ctx[4 * f + 3] * alpha);
            }
            m = mn;
        }
        float inv = 1.f / l;
        float4* op = (float4*)(CTX + ((size_t)b * TOTAL + tq) * EMBED
                               + h * HEAD_DIM + half * 32);
#pragma unroll
        for (int f = 0; f < 8; f++)
            op[f] = cvt4(make_float4(ctx[4 * f + 0] * inv, ctx[4 * f + 1] * inv,
                                     ctx[4 * f + 2] * inv, ctx[4 * f + 3] * inv));
    }
}

// ---------------------------------------------------------------------------
// Attention, SUM queries. One warp per (b, h, s); qkv fused buffer.
// ---------------------------------------------------------------------------
__global__ __launch_bounds__(256) void attn_sum_kernel(
    const float* __restrict__ QKV, const int* __restrict__ ranges,
    float* __restrict__ CTX)
{
    int gw = (blockIdx.x * blockDim.x + threadIdx.x) >> 5;
    int lane = threadIdx.x & 31;
    if (gw >= BSZ * HEADS * SUM_LEN) return;
    int b = gw / (HEADS * SUM_LEN);
    int rem = gw % (HEADS * SUM_LEN);
    int h = rem / SUM_LEN;
    int s = rem % SUM_LEN;

    int start = ranges[(b * NCHUNK + s) * 2];
    int next  = (s + 1 < NCHUNK) ? ranges[(b * NCHUNK + s + 1) * 2] : REG_LEN;

    size_t bbase = (size_t)b * TOTAL;
    float2 q2 = ((const float2*)(QKV + (bbase + s) * QKV_STR + h * HEAD_DIM))[lane];
    q2.x *= 0.125f; q2.y *= 0.125f;

    float m = -1e30f, l = 0.f, cx = 0.f, cy = 0.f;

#define ASTEP(tok_expr)                                                                 \
    do {                                                                                \
        int tok = (tok_expr);                                                           \
        size_t ko = (bbase + tok) * QKV_STR + h * HEAD_DIM;                             \
        float2 kk = ((const float2*)(QKV + ko + 1024))[lane];                           \
        float part = q2.x * kk.x + q2.y * kk.y;                                         \
        _Pragma("unroll")                                                               \
        for (int o = 16; o; o >>= 1) part += __shfl_xor_sync(0xffffffffu, part, o);     \
        float mn = fmaxf(m, part);                                                      \
        float alpha = __expf(m - mn);                                                   \
        float p = __expf(part - mn);                                                    \
        l = l * alpha + p;                                                              \
        float2 vv = ((const float2*)(QKV + ko + 2048))[lane];                           \
        cx = fmaf(p, vv.x, cx * alpha);                                                 \
        cy = fmaf(p, vv.y, cy * alpha);                                                 \
        m = mn;                                                                         \
    } while (0)

    for (int t = 0; t <= s; t++)       ASTEP(t);
    for (int t = start; t < next; t++) ASTEP(SUM_LEN + t);
#undef ASTEP

    float inv = 1.f / l;
    ((float2*)(CTX + (bbase + s) * EMBED + h * HEAD_DIM))[lane] =
        make_float2(f2tf32(cx * inv), f2tf32(cy * inv));
}

// ---------------------------------------------------------------------------
// Launch sequence
// ---------------------------------------------------------------------------
extern "C" void kernel_launch(void* const* d_in, const int* in_sizes, int n_in,
                              void* d_out, int out_size)
{
    const float* x      = (const float*)d_in[0];
    const float* w_q    = (const float*)d_in[1];
    const float* w_k    = (const float*)d_in[2];
    const float* w_v    = (const float*)d_in[3];
    const float* w_o    = (const float*)d_in[4];
    const float* ln1_sg = (const float*)d_in[5];
    const float* ln1_sb = (const float*)d_in[6];
    const float* ln1_rg = (const float*)d_in[7];
    const float* ln1_rb = (const float*)d_in[8];
    const float* sfc1w  = (const float*)d_in[9];
    const float* sfc1b  = (const float*)d_in[10];
    const float* sfc2w  = (const float*)d_in[11];
    const float* sfc2b  = (const float*)d_in[12];
    const float* rfc1w  = (const float*)d_in[13];
    const float* rfc1b  = (const float*)d_in[14];
    const float* rfc2w  = (const float*)d_in[15];
    const float* rfc2b  = (const float*)d_in[16];
    const float* ln2_sg = (const float*)d_in[17];
    const float* ln2_sb = (const float*)d_in[18];
    const float* ln2_rg = (const float*)d_in[19];
    const float* ln2_rb = (const float*)d_in[20];
    const int*   ranges = (const int*)d_in[21];
    float* out = (float*)d_out;

    void *ph, *pctx, *px1, *ph2, *pmid, *pwr;
    cudaGetSymbolAddress(&ph,   g_h);
    cudaGetSymbolAddress(&pctx, g_ctx);
    cudaGetSymbolAddress(&px1,  g_x1);
    cudaGetSymbolAddress(&ph2,  g_h2);
    cudaGetSymbolAddress(&pmid, g_mid);
    cudaGetSymbolAddress(&pwr,  g_wr);
    float* h   = (float*)ph;
    float* ctx = (float*)pctx;
    float* x1  = (float*)px1;
    float* h2  = (float*)ph2;
    float* mid = (float*)pmid;   // first used as fused qkv [NTOK, 3072]
    float* wr  = (float*)pwr;

    const size_t zE = (size_t)TOTAL * EMBED;
    const size_t zF = (size_t)TOTAL * FFN_DIM;

    cudaFuncSetAttribute(attn_reg_kernel,
                         cudaFuncAttributeMaxDynamicSharedMemorySize, ATTN_SMEM);
    cudaFuncSetAttribute(gemm_tc<false, false, false, false>,
                         cudaFuncAttributeMaxDynamicSharedMemorySize, GEMM_SMEM);
    cudaFuncSetAttribute(gemm_tc<false, false, true, false>,
                         cudaFuncAttributeMaxDynamicSharedMemorySize, GEMM_SMEM);
    cudaFuncSetAttribute(gemm_tc<true, true, false, true>,
                         cudaFuncAttributeMaxDynamicSharedMemorySize, GEMM_SMEM);
    cudaFuncSetAttribute(gemm_tc<false, true, true, false>,
                         cudaFuncAttributeMaxDynamicSharedMemorySize, GEMM_SMEM);

    // 0) Round ALL weights to tf32 (rna) in one launch
    {
        RoundSrcs rs;
        rs.s[0] = (const float4*)w_q;   rs.s[1] = (const float4*)w_k;
        rs.s[2] = (const float4*)w_v;   rs.s[3] = (const float4*)w_o;
        rs.s[4] = (const float4*)sfc1w; rs.s[5] = (const float4*)sfc2w;
        rs.s[6] = (const float4*)rfc1w; rs.s[7] = (const float4*)rfc2w;
        round_all_kernel<<<20480, 256>>>(rs, (float4*)wr);
    }

    // 1) LN1 (tf32-rounded output)
    ln_kernel<<<NTOK, 256>>>(x, ln1_sg, ln1_sb, ln1_rg, ln1_rb, h);

    // 2) Fused QKV projection: [NTOK,1024] @ [3072,1024]^T -> mid [NTOK,3072]
    gemm_tc<false, false, false, false><<<dim3(24, 33, 1), 256, GEMM_SMEM>>>(
        h, wr + WR_WQ, mid, NTOK, QKV_STR, EMBED, nullptr, nullptr, 0, 0, 0);

    // 3) Sparse masked attention (ctx rounded to tf32)
    attn_reg_kernel<<<dim3(NCHUNK, HEADS, BSZ), 256, ATTN_SMEM>>>(mid, ranges, ctx);
    attn_sum_kernel<<<(BSZ * HEADS * SUM_LEN) / 8, 256>>>(mid, ranges, ctx);

    // 4) Output projection + residual: x1 = x + ctx @ Wo^T
    gemm_tc<false, false, true, false><<<dim3(8, 33, 1), 256, GEMM_SMEM>>>(
        ctx, wr + WR_WO, x1, NTOK, EMBED, EMBED, nullptr, x, 0, 0, 0);

    // 5) LN2 (rounded)
    ln_kernel<<<NTOK, 256>>>(x1, ln2_sg, ln2_sb, ln2_rg, ln2_rb, h2);

    // 6) FFN — reg segments (M=2048, batched z=2)
    gemm_tc<true, true, false, true><<<dim3(32, 16, BSZ), 256, GEMM_SMEM>>>(
        h2 + (size_t)SUM_LEN * EMBED, wr + WR_RFC1, mid + (size_t)SUM_LEN * FFN_DIM,
        REG_LEN, FFN_DIM, EMBED, rfc1b, nullptr, zE, zF, 0);
    gemm_tc<false, true, true, false><<<dim3(8, 16, BSZ), 256, GEMM_SMEM>>>(
        mid + (size_t)SUM_LEN * FFN_DIM, wr + WR_RFC2, out + (size_t)SUM_LEN * EMBED,
        REG_LEN, EMBED, FFN_DIM, rfc2b, x1 + (size_t)SUM_LEN * EMBED, zF, zE, zE);

    //    sum segments (M=16, batched z=2)
    gemm_tc<true, true, false, true><<<dim3(32, 1, BSZ), 256, GEMM_SMEM>>>(
        h2, wr + WR_SFC1, mid, SUM_LEN, FFN_DIM, EMBED, sfc1b, nullptr, zE, zF, 0);
    gemm_tc<false, true, true, false><<<dim3(8, 1, BSZ), 256, GEMM_SMEM>>>(
        mid, wr + WR_SFC2, out, SUM_LEN, EMBED, FFN_DIM, sfc2b, x1, zF, zE, zE);
}

// round 10
// speedup vs baseline: 5.2033x; 1.1936x over previous
#include <cuda_runtime.h>
#include <cstdint>
#include <cstddef>

// ---------------------------------------------------------------------------
#define EMBED    1024
#define HEADS    16
#define HEAD_DIM 64
#define FFN_DIM  4096
#define BSZ      2
#define SUM_LEN  16
#define REG_LEN  2048
#define TOTAL    (SUM_LEN + REG_LEN)   // 2064
#define NCHUNK   16
#define NTOK     (BSZ * TOTAL)         // 4128
#define QKV_STR  3072                  // fused qkv row stride

// tensor-core attention tile constants
#define PADK   144                     // keys padded (max 15 sum + 128 reg + pad)
#define VSTR   148                     // Vt row stride in floats (bank spread)
#define QS_OFF 0                       // floats
#define KS_OFF 8192
#define VT_OFF 17408
#define ATTN_SMEM ((VT_OFF + 64 * VSTR) * 4)   // 107,520 bytes

// ---------------------------------------------------------------------------
// Static device scratch (no cudaMalloc allowed)
// ---------------------------------------------------------------------------
__device__ __align__(1024) float g_h  [(size_t)NTOK * EMBED];
__device__ __align__(1024) float g_ctx[(size_t)NTOK * EMBED];
__device__ __align__(1024) float g_x1 [(size_t)NTOK * EMBED];
__device__ __align__(1024) float g_h2 [(size_t)NTOK * EMBED];
__device__ __align__(1024) float g_mid[(size_t)NTOK * FFN_DIM];  // qkv, then ffn mid
// tf32-rounded weights (wq|wk|wv contiguous => fused qkv B matrix)
#define WR_WQ   ((size_t)0)
#define WR_WO   ((size_t)3  * 1024 * 1024)
#define WR_SFC1 ((size_t)4  * 1024 * 1024)
#define WR_SFC2 ((size_t)8  * 1024 * 1024)
#define WR_RFC1 ((size_t)12 * 1024 * 1024)
#define WR_RFC2 ((size_t)16 * 1024 * 1024)
__device__ __align__(1024) float g_wr[(size_t)20 * 1024 * 1024];

// ---------------------------------------------------------------------------
// PTX helpers
// ---------------------------------------------------------------------------
__device__ __forceinline__ uint32_t smem_u32(const void* p) {
    uint32_t a;
    asm("{ .reg .u64 t; cvta.to.shared.u64 t, %1; cvt.u32.u64 %0, t; }"
        : "=r"(a) : "l"(p));
    return a;
}
__device__ __forceinline__ float f2tf32(float f) {
    unsigned u;
    asm("cvt.rna.tf32.f32 %0, %1;" : "=r"(u) : "f"(f));
    return __uint_as_float(u);
}
__device__ __forceinline__ float4 cvt4(float4 v) {
    return make_float4(f2tf32(v.x), f2tf32(v.y), f2tf32(v.z), f2tf32(v.w));
}
__device__ __forceinline__ void mma_tf32(float* d, const unsigned* a, const unsigned* b) {
    asm volatile(
        "mma.sync.aligned.m16n8k8.row.col.f32.tf32.tf32.f32 "
        "{%0,%1,%2,%3}, {%4,%5,%6,%7}, {%8,%9}, {%0,%1,%2,%3};"
        : "+f"(d[0]), "+f"(d[1]), "+f"(d[2]), "+f"(d[3])
        : "r"(a[0]), "r"(a[1]), "r"(a[2]), "r"(a[3]), "r"(b[0]), "r"(b[1]));
}
__device__ __forceinline__ void ldsm_x4(unsigned* r, uint32_t addr) {
    asm volatile("ldmatrix.sync.aligned.m8n8.x4.shared.b16 {%0,%1,%2,%3}, [%4];"
                 : "=r"(r[0]), "=r"(r[1]), "=r"(r[2]), "=r"(r[3]) : "r"(addr));
}
#define CP_ASYNC16(dst, src, sz) \
    asm volatile("cp.async.cg.shared.global [%0], [%1], 16, %2;" \
                 :: "r"(dst), "l"(src), "r"(sz) : "memory")
#define CP_COMMIT() asm volatile("cp.async.commit_group;" ::: "memory")
#define CP_WAIT2()  asm volatile("cp.async.wait_group 2;" ::: "memory")

// ---------------------------------------------------------------------------
// TF32 tensor-core GEMM (NT), optional folded second problem on last y-block.
// 128x128 tile, BK=16, 256 threads (8 warps 4x2), cp.async 4-stage, 1 sync/iter.
// ---------------------------------------------------------------------------
#define STAGES 4
#define STAGE_BYTES 16384
#define GEMM_SMEM (STAGES * STAGE_BYTES)

template<bool RELU, bool HAS_BIAS, bool HAS_RESID, bool ROUND_OUT, bool FOLD>
__global__ __launch_bounds__(256) void gemm_tc(
    const float* __restrict__ A, const float* __restrict__ B,
    float* __restrict__ C, int M, int NC, int K,
    const float* __restrict__ bias, const float* __restrict__ resid,
    size_t zA, size_t zC, size_t zR,
    const float* A2, const float* B2, const float* bias2,
    const float* resid2, float* C2)
{
    extern __shared__ char smraw[];
    const uint32_t smb = smem_u32(smraw);

    const bool sumblk = FOLD && (blockIdx.y == gridDim.y - 1);
    if (sumblk) { A = A2; B = B2; bias = bias2; resid = resid2; C = C2; M = SUM_LEN; }
    const int by = sumblk ? 0 : blockIdx.y;

    A += (size_t)blockIdx.z * zA;
    C += (size_t)blockIdx.z * zC;
    if (HAS_RESID) resid += (size_t)blockIdx.z * zR;

    const int tid  = threadIdx.x;
    const int lane = tid & 31;
    const int warp = tid >> 5;
    const int wm   = (warp >> 1) * 32;
    const int wn   = (warp & 1) * 64;

    const int srow = tid >> 1;
    const int scol = (tid & 1) * 2;
    const int rowA = by * 128 + srow;
    const int rowB = blockIdx.x * 128 + srow;
    const uint32_t asz = (rowA < M) ? 16u : 0u;
    const float* Ag = A + (size_t)(rowA < M ? rowA : 0) * K + scol * 4;
    const float* Bg = B + (size_t)rowB * K + scol * 4;
    const uint32_t ssw  = (srow >> 1) & 3;
    const uint32_t dst0 = srow * 64 + (((uint32_t)scol ^ ssw) << 4);
    const uint32_t dst1 = srow * 64 + ((((uint32_t)scol + 1) ^ ssw) << 4);

    const int arow0 = wm + (lane & 15);
    const uint32_t aoff0 = arow0 * 64,        ask0 = (arow0 >> 1) & 3;
    const uint32_t aoff1 = (arow0 + 16) * 64, ask1 = ((arow0 + 16) >> 1) & 3;
    const uint32_t acb = lane >> 4;
    const int bn = wn + ((lane >> 4) << 3) + (lane & 7);
    const uint32_t bcb = (lane >> 3) & 1;
    uint32_t boff[4], bsk[4];
#pragma unroll
    for (int p = 0; p < 4; p++) {
        int n = bn + p * 16;
        boff[p] = n * 64;
        bsk[p]  = (n >> 1) & 3;
    }

    float acc[2][8][4];
#pragma unroll
    for (int mt = 0; mt < 2; mt++)
#pragma unroll
        for (int nt = 0; nt < 8; nt++)
#pragma unroll
            for (int i = 0; i < 4; i++) acc[mt][nt][i] = 0.f;

    const int nstep = K >> 4;

#pragma unroll
    for (int s = 0; s < STAGES - 1; s++) {
        uint32_t ab = smb + s * STAGE_BYTES;
        uint32_t bb = ab + 8192;
        const float* ag = Ag + s * 16;
        const float* bg = Bg + s * 16;
        CP_ASYNC16(ab + dst0, ag,     asz);
        CP_ASYNC16(ab + dst1, ag + 4, asz);
        CP_ASYNC16(bb + dst0, bg,     16u);
        CP_ASYNC16(bb + dst1, bg + 4, 16u);
        CP_COMMIT();
    }

    for (int i = 0; i < nstep; i++) {
        CP_WAIT2();
        __syncthreads();

        const int nf = i + STAGES - 1;
        if (nf < nstep) {
            uint32_t ab = smb + (nf % STAGES) * STAGE_BYTES;
            uint32_t bb = ab + 8192;
            const float* ag = Ag + nf * 16;
            const float* bg = Bg + nf * 16;
            CP_ASYNC16(ab + dst0, ag,     asz);
            CP_ASYNC16(ab + dst1, ag + 4, asz);
            CP_ASYNC16(bb + dst0, bg,     16u);
            CP_ASYNC16(bb + dst1, bg + 4, 16u);
        }
        CP_COMMIT();

        const uint32_t ab = smb + (i % STAGES) * STAGE_BYTES;
        const uint32_t bb = ab + 8192;

#pragma unroll
        for (int sub = 0; sub < 2; sub++) {
            const uint32_t ch = sub * 2 + acb;
            unsigned a0[4], a1[4], b[4][4];
            ldsm_x4(a0, ab + aoff0 + ((ch ^ ask0) << 4));
            ldsm_x4(a1, ab + aoff1 + ((ch ^ ask1) << 4));
            const uint32_t chb = sub * 2 + bcb;
#pragma unroll
            for (int p = 0; p < 4; p++)
                ldsm_x4(b[p], bb + boff[p] + ((chb ^ bsk[p]) << 4));
#pragma unroll
            for (int p = 0; p < 4; p++) {
                mma_tf32(acc[0][2 * p    ], a0, &b[p][0]);
                mma_tf32(acc[0][2 * p + 1], a0, &b[p][2]);
                mma_tf32(acc[1][2 * p    ], a1, &b[p][0]);
                mma_tf32(acc[1][2 * p + 1], a1, &b[p][2]);
            }
        }
    }

    const int fr = lane >> 2, fk = lane & 3;
    const int rowbase = by * 128 + wm + fr;
    const int colbase = blockIdx.x * 128 + wn + fk * 2;
#pragma unroll
    for (int mt = 0; mt < 2; mt++) {
#pragma unroll
        for (int half = 0; half < 2; half++) {
            int r = rowbase + mt * 16 + half * 8;
            if (r >= M) continue;
#pragma unroll
            for (int nt = 0; nt < 8; nt++) {
                int cidx = colbase + nt * 8;
                float v0 = acc[mt][nt][half * 2 + 0];
                float v1 = acc[mt][nt][half * 2 + 1];
                if (HAS_BIAS) { v0 += bias[cidx]; v1 += bias[cidx + 1]; }
                if (RELU) { v0 = fmaxf(v0, 0.f); v1 = fmaxf(v1, 0.f); }
                if (HAS_RESID) {
                    float2 rr = *(const float2*)(resid + (size_t)r * NC + cidx);
                    v0 += rr.x; v1 += rr.y;
                }
                if (ROUND_OUT) { v0 = f2tf32(v0); v1 = f2tf32(v1); }
                *(float2*)(C + (size_t)r * NC + cidx) = make_float2(v0, v1);
            }
        }
    }
}

// ---------------------------------------------------------------------------
// Fused weight rounding (one launch)
// ---------------------------------------------------------------------------
struct RoundSrcs { const float4* s[8]; };

__global__ __launch_bounds__(256) void round_all_kernel(
    RoundSrcs srcs, float4* __restrict__ dst)
{
    size_t i = (size_t)blockIdx.x * 256 + threadIdx.x;   // < 5242880
    int r; size_t base;
    if (i < 1048576) { r = (int)(i >> 18);     base = (size_t)r << 18; }
    else             { r = 3 + (int)(i >> 20); base = (size_t)(r - 3) << 20; }
    dst[i] = cvt4(srcs.s[r][i - base]);
}

// ---------------------------------------------------------------------------
// LayerNorm (output rounded to tf32)
// ---------------------------------------------------------------------------
__global__ __launch_bounds__(256) void ln_kernel(
    const float* __restrict__ x,
    const float* __restrict__ gs, const float* __restrict__ bs,
    const float* __restrict__ gr, const float* __restrict__ br,
    float* __restrict__ out)
{
    int row = blockIdx.x;
    int t = row % TOTAL;
    const float* g = (t < SUM_LEN) ? gs : gr;
    const float* b = (t < SUM_LEN) ? bs : br;
    int tid = threadIdx.x;
    int lane = tid & 31, warp = tid >> 5;

    float4 v = ((const float4*)(x + (size_t)row * EMBED))[tid];
    float s = v.x + v.y + v.z + v.w;
    float q = v.x * v.x + v.y * v.y + v.z * v.z + v.w * v.w;

    __shared__ float rs_[8], rq_[8];
#pragma unroll
    for (int o = 16; o; o >>= 1) {
        s += __shfl_xor_sync(0xffffffffu, s, o);
        q += __shfl_xor_sync(0xffffffffu, q, o);
    }
    if (lane == 0) { rs_[warp] = s; rq_[warp] = q; }
    __syncthreads();
    if (tid < 32) {
        s = (lane < 8) ? rs_[lane] : 0.f;
        q = (lane < 8) ? rq_[lane] : 0.f;
#pragma unroll
        for (int o = 4; o; o >>= 1) {
            s += __shfl_xor_sync(0xffffffffu, s, o);
            q += __shfl_xor_sync(0xffffffffu, q, o);
        }
        if (lane == 0) { rs_[0] = s; rq_[0] = q; }
    }
    __syncthreads();

    float mean = rs_[0] * (1.f / EMBED);
    float var  = rq_[0] * (1.f / EMBED) - mean * mean;
    float rinv = rsqrtf(var + 1e-5f);

    float4 gg = ((const float4*)g)[tid];
    float4 bb = ((const float4*)b)[tid];
    float4 o4;
    o4.x = (v.x - mean) * rinv * gg.x + bb.x;
    o4.y = (v.y - mean) * rinv * gg.y + bb.y;
    o4.z = (v.z - mean) * rinv * gg.z + bb.z;
    o4.w = (v.w - mean) * rinv * gg.w + bb.w;
    ((float4*)(out + (size_t)row * EMBED))[tid] = cvt4(o4);
}

// ---------------------------------------------------------------------------
// TENSOR-CORE attention for REG queries. Grid (NCHUNK, HEADS, BSZ), 256 thr.
// Per CTA: S = Qs @ Ks^T (tf32 mma), mask, softmax, O = P @ V (Vt in smem).
// Frag conventions identical to gemm_tc (hardware-validated).
// ---------------------------------------------------------------------------
__global__ __launch_bounds__(256) void attn_reg_kernel(
    const float* __restrict__ QKV, const int* __restrict__ ranges,
    float* __restrict__ CTX)
{
    extern __shared__ float sm[];
    const uint32_t smb = smem_u32(sm);
    const uint32_t QS = smb + QS_OFF * 4;
    const uint32_t KS = smb + KS_OFF * 4;
    const uint32_t VT = smb + VT_OFF * 4;

    const int c = blockIdx.x, h = blockIdx.y, b = blockIdx.z;
    const int start = ranges[(b * NCHUNK + c) * 2];
    const int next  = (c + 1 < NCHUNK) ? ranges[(b * NCHUNK + c + 1) * 2] : REG_LEN;
    const int width = next - start;
    const int nsum  = c;
    const int nk    = nsum + width;
    const size_t bb = (size_t)b * TOTAL;

    const int tid = threadIdx.x;

    // ---- stage Q (scaled 0.125, tf32-rounded), swizzled 16B chunks ----
    for (int idx = tid; idx < 128 * 16; idx += 256) {
        int row = idx >> 4, ch = idx & 15;
        int tok = SUM_LEN + start + row;
        float4 t4 = *(const float4*)(QKV + (bb + tok) * QKV_STR + h * HEAD_DIM + ch * 4);
        t4.x *= 0.125f; t4.y *= 0.125f; t4.z *= 0.125f; t4.w *= 0.125f;
        *(float4*)(sm + QS_OFF + row * 64 + ((ch ^ (row & 15)) << 2)) = cvt4(t4);
    }
    // ---- stage K (padded to PADK rows, zero fill), swizzled ----
    for (int idx = tid; idx < PADK * 16; idx += 256) {
        int j = idx >> 4, ch = idx & 15;
        float4 t4 = make_float4(0.f, 0.f, 0.f, 0.f);
        if (j < nk) {
            int tok = (j < nsum) ? j : (SUM_LEN + start + (j - nsum));
            t4 = cvt4(*(const float4*)(QKV + (bb + tok) * QKV_STR + h * HEAD_DIM
                                       + 1024 + ch * 4));
        }
        *(float4*)(sm + KS_OFF + j * 64 + ((ch ^ (j & 15)) << 2)) = t4;
    }
    // ---- stage V transposed: Vt[dim][key], zero-padded keys ----
    for (int idx = tid; idx < PADK * 16; idx += 256) {
        int j = idx >> 4, ch = idx & 15;
        float4 t4 = make_float4(0.f, 0.f, 0.f, 0.f);
        if (j < nk) {
            int tok = (j < nsum) ? j : (SUM_LEN + start + (j - nsum));
            t4 = cvt4(*(const float4*)(QKV + (bb + tok) * QKV_STR + h * HEAD_DIM
                                       + 2048 + ch * 4));
        }
        int d = ch * 4;
        sm[VT_OFF + (d + 0) * VSTR + j] = t4.x;
        sm[VT_OFF + (d + 1) * VSTR + j] = t4.y;
        sm[VT_OFF + (d + 2) * VSTR + j] = t4.z;
        sm[VT_OFF + (d + 3) * VSTR + j] = t4.w;
    }
    __syncthreads();

    const int lane = tid & 31, wid = tid >> 5;
    const int fr = lane >> 2, fk = lane & 3;

    // ---- phase 1: S[128,144] = Q @ K^T ----
    float S[18][4];
#pragma unroll
    for (int t = 0; t < 18; t++)
#pragma unroll
        for (int i = 0; i < 4; i++) S[t][i] = 0.f;

    {
        const int arow = wid * 16 + (lane & 15);
        const uint32_t abase = QS + (arow * 64) * 4;
        const uint32_t asw   = (arow & 15);
        const int krow = 16 * ((lane >> 4) << 0) * 0 + ((lane >> 4) << 3) + (lane & 7);
        const uint32_t kcb = (lane >> 3) & 1;
#pragma unroll
        for (int k8 = 0; k8 < 8; k8++) {
            unsigned a[4];
            uint32_t ach = 2 * k8 + (lane >> 4);
            ldsm_x4(a, abase + ((ach ^ asw) << 4));
            uint32_t bch = 2 * k8 + kcb;
#pragma unroll
            for (int p = 0; p < 9; p++) {
                unsigned bf[4];
                int kr = 16 * p + krow;
                ldsm_x4(bf, KS + (kr * 64) * 4 + ((bch ^ (uint32_t)(kr & 15)) << 4));
                mma_tf32(S[2 * p],     a, &bf[0]);
                mma_tf32(S[2 * p + 1], a, &bf[2]);
            }
        }
    }

    // ---- mask + softmax ----
    const int q0 = wid * 16 + fr;              // query row, and q0+8
    const int lim0 = nsum + q0, lim1 = lim0 + 8;
    float m0 = -1e30f, m1 = -1e30f;
#pragma unroll
    for (int t = 0; t < 18; t++) {
        int cb = 8 * t + 2 * fk;
        S[t][0] = (cb     <= lim0) ? S[t][0] : -1e30f;
        S[t][1] = (cb + 1 <= lim0) ? S[t][1] : -1e30f;
        S[t][2] = (cb     <= lim1) ? S[t][2] : -1e30f;
        S[t][3] = (cb + 1 <= lim1) ? S[t][3] : -1e30f;
        m0 = fmaxf(m0, fmaxf(S[t][0], S[t][1]));
        m1 = fmaxf(m1, fmaxf(S[t][2], S[t][3]));
    }
    m0 = fmaxf(m0, __shfl_xor_sync(0xffffffffu, m0, 1));
    m0 = fmaxf(m0, __shfl_xor_sync(0xffffffffu, m0, 2));
    m1 = fmaxf(m1, __shfl_xor_sync(0xffffffffu, m1, 1));
    m1 = fmaxf(m1, __shfl_xor_sync(0xffffffffu, m1, 2));

    float l0 = 0.f, l1 = 0.f;
#pragma unroll
    for (int t = 0; t < 18; t++) {
        S[t][0] = f2tf32(__expf(S[t][0] - m0));
        S[t][1] = f2tf32(__expf(S[t][1] - m0));
        S[t][2] = f2tf32(__expf(S[t][2] - m1));
        S[t][3] = f2tf32(__expf(S[t][3] - m1));
        l0 += S[t][0] + S[t][1];
        l1 += S[t][2] + S[t][3];
    }
    l0 += __shfl_xor_sync(0xffffffffu, l0, 1);
    l0 += __shfl_xor_sync(0xffffffffu, l0, 2);
    l1 += __shfl_xor_sync(0xffffffffu, l1, 1);
    l1 += __shfl_xor_sync(0xffffffffu, l1, 2);

    // ---- phase 2: O = P @ V (C-frag -> A-frag via shfl) ----
    float O[8][4];
#pragma unroll
    for (int nt = 0; nt < 8; nt++)
#pragma unroll
        for (int i = 0; i < 4; i++) O[nt][i] = 0.f;

    const int s0 = (lane & ~3) | (fk >> 1);
    const int s1 = s0 + 2;
    const bool e = fk & 1;
    const int vrow0 = ((lane >> 4) << 3) + (lane & 7);
    const uint32_t vcb = (lane >> 3) & 1;

#pragma unroll
    for (int t = 0; t < 18; t++) {
        float x0 = __shfl_sync(0xffffffffu, S[t][0], s0);
        float x1 = __shfl_sync(0xffffffffu, S[t][1], s0);
        float x2 = __shfl_sync(0xffffffffu, S[t][2], s0);
        float x3 = __shfl_sync(0xffffffffu, S[t][3], s0);
        float y0 = __shfl_sync(0xffffffffu, S[t][0], s1);
        float y1 = __shfl_sync(0xffffffffu, S[t][1], s1);
        float y2 = __shfl_sync(0xffffffffu, S[t][2], s1);
        float y3 = __shfl_sync(0xffffffffu, S[t][3], s1);
        unsigned a[4];
        a[0] = __float_as_uint(e ? x1 : x0);
        a[1] = __float_as_uint(e ? x3 : x2);
        a[2] = __float_as_uint(e ? y1 : y0);
        a[3] = __float_as_uint(e ? y3 : y2);
        const uint32_t vch = (2 * t + vcb) << 4;
#pragma unroll
        for (int pn = 0; pn < 4; pn++) {
            unsigned bf[4];
            int vr = 16 * pn + vrow0;
            ldsm_x4(bf, VT + (vr * VSTR) * 4 + vch);
            mma_tf32(O[2 * pn],     a, &bf[0]);
            mma_tf32(O[2 * pn + 1], a, &bf[2]);
        }
    }

    // ---- normalize + store ----
    const float inv0 = 1.f / l0, inv1 = 1.f / l1;
    if (q0 < width) {
        int tok = SUM_LEN + start + q0;
        float* op = CTX + (bb + tok) * EMBED + h * HEAD_DIM + 2 * fk;
#pragma unroll
        for (int nt = 0; nt < 8; nt++)
            *(float2*)(op + 8 * nt) =
                make_float2(f2tf32(O[nt][0] * inv0), f2tf32(O[nt][1] * inv0));
    }
    if (q0 + 8 < width) {
        int tok = SUM_LEN + start + q0 + 8;
        float* op = CTX + (bb + tok) * EMBED + h * HEAD_DIM + 2 * fk;
#pragma unroll
        for (int nt = 0; nt < 8; nt++)
            *(float2*)(op + 8 * nt) =
                make_float2(f2tf32(O[nt][2] * inv1), f2tf32(O[nt][3] * inv1));
    }
}

// ---------------------------------------------------------------------------
// Attention, SUM queries. One warp per (b, h, s); qkv fused buffer.
// ---------------------------------------------------------------------------
__global__ __launch_bounds__(256) void attn_sum_kernel(
    const float* __restrict__ QKV, const int* __restrict__ ranges,
    float* __restrict__ CTX)
{
    int gw = (blockIdx.x * blockDim.x + threadIdx.x) >> 5;
    int lane = threadIdx.x & 31;
    if (gw >= BSZ * HEADS * SUM_LEN) return;
    int b = gw / (HEADS * SUM_LEN);
    int rem = gw % (HEADS * SUM_LEN);
    int h = rem / SUM_LEN;
    int s = rem % SUM_LEN;

    int start = ranges[(b * NCHUNK + s) * 2];
    int next  = (s + 1 < NCHUNK) ? ranges[(b * NCHUNK + s + 1) * 2] : REG_LEN;

    size_t bbase = (size_t)b * TOTAL;
    float2 q2 = ((const float2*)(QKV + (bbase + s) * QKV_STR + h * HEAD_DIM))[lane];
    q2.x *= 0.125f; q2.y *= 0.125f;

    float m = -1e30f, l = 0.f, cx = 0.f, cy = 0.f;

#define ASTEP(tok_expr)                                                                 \
    do {                                                                                \
        int tok = (tok_expr);                                                           \
        size_t ko = (bbase + tok) * QKV_STR + h * HEAD_DIM;                             \
        float2 kk = ((const float2*)(QKV + ko + 1024))[lane];                           \
        float part = q2.x * kk.x + q2.y * kk.y;                                         \
        _Pragma("unroll")                                                               \
        for (int o = 16; o; o >>= 1) part += __shfl_xor_sync(0xffffffffu, part, o);     \
        float mn = fmaxf(m, part);                                                      \
        float alpha = __expf(m - mn);                                                   \
        float p = __expf(part - mn);                                                    \
        l = l * alpha + p;                                                              \
        float2 vv = ((const float2*)(QKV + ko + 2048))[lane];                           \
        cx = fmaf(p, vv.x, cx * alpha);                                                 \
        cy = fmaf(p, vv.y, cy * alpha);                                                 \
        m = mn;                                                                         \
    } while (0)

    for (int t = 0; t <= s; t++)       ASTEP(t);
    for (int t = start; t < next; t++) ASTEP(SUM_LEN + t);
#undef ASTEP

    float inv = 1.f / l;
    ((float2*)(CTX + (bbase + s) * EMBED + h * HEAD_DIM))[lane] =
        make_float2(f2tf32(cx * inv), f2tf32(cy * inv));
}

// ---------------------------------------------------------------------------
// Launch sequence
// ---------------------------------------------------------------------------
extern "C" void kernel_launch(void* const* d_in, const int* in_sizes, int n_in,
                              void* d_out, int out_size)
{
    const float* x      = (const float*)d_in[0];
    const float* w_q    = (const float*)d_in[1];
    const float* w_k    = (const float*)d_in[2];
    const float* w_v    = (const float*)d_in[3];
    const float* w_o    = (const float*)d_in[4];
    const float* ln1_sg = (const float*)d_in[5];
    const float* ln1_sb = (const float*)d_in[6];
    const float* ln1_rg = (const float*)d_in[7];
    const float* ln1_rb = (const float*)d_in[8];
    const float* sfc1w  = (const float*)d_in[9];
    const float* sfc1b  = (const float*)d_in[10];
    const float* sfc2w  = (const float*)d_in[11];
    const float* sfc2b  = (const float*)d_in[12];
    const float* rfc1w  = (const float*)d_in[13];
    const float* rfc1b  = (const float*)d_in[14];
    const float* rfc2w  = (const float*)d_in[15];
    const float* rfc2b  = (const float*)d_in[16];
    const float* ln2_sg = (const float*)d_in[17];
    const float* ln2_sb = (const float*)d_in[18];
    const float* ln2_rg = (const float*)d_in[19];
    const float* ln2_rb = (const float*)d_in[20];
    const int*   ranges = (const int*)d_in[21];
    float* out = (float*)d_out;

    void *ph, *pctx, *px1, *ph2, *pmid, *pwr;
    cudaGetSymbolAddress(&ph,   g_h);
    cudaGetSymbolAddress(&pctx, g_ctx);
    cudaGetSymbolAddress(&px1,  g_x1);
    cudaGetSymbolAddress(&ph2,  g_h2);
    cudaGetSymbolAddress(&pmid, g_mid);
    cudaGetSymbolAddress(&pwr,  g_wr);
    float* h   = (float*)ph;
    float* ctx = (float*)pctx;
    float* x1  = (float*)px1;
    float* h2  = (float*)ph2;
    float* mid = (float*)pmid;
    float* wr  = (float*)pwr;

    const size_t zE = (size_t)TOTAL * EMBED;
    const size_t zF = (size_t)TOTAL * FFN_DIM;

    cudaFuncSetAttribute(attn_reg_kernel,
                         cudaFuncAttributeMaxDynamicSharedMemorySize, ATTN_SMEM);
    cudaFuncSetAttribute(gemm_tc<false, false, false, false, false>,
                         cudaFuncAttributeMaxDynamicSharedMemorySize, GEMM_SMEM);
    cudaFuncSetAttribute(gemm_tc<false, false, true, false, false>,
                         cudaFuncAttributeMaxDynamicSharedMemorySize, GEMM_SMEM);
    cudaFuncSetAttribute(gemm_tc<true, true, false, true, true>,
                         cudaFuncAttributeMaxDynamicSharedMemorySize, GEMM_SMEM);
    cudaFuncSetAttribute(gemm_tc<false, true, true, false, true>,
                         cudaFuncAttributeMaxDynamicSharedMemorySize, GEMM_SMEM);

    // 0) Round ALL weights to tf32 (rna) in one launch
    {
        RoundSrcs rs;
        rs.s[0] = (const float4*)w_q;   rs.s[1] = (const float4*)w_k;
        rs.s[2] = (const float4*)w_v;   rs.s[3] = (const float4*)w_o;
        rs.s[4] = (const float4*)sfc1w; rs.s[5] = (const float4*)sfc2w;
        rs.s[6] = (const float4*)rfc1w; rs.s[7] = (const float4*)rfc2w;
        round_all_kernel<<<20480, 256>>>(rs, (float4*)wr);
    }

    // 1) LN1
    ln_kernel<<<NTOK, 256>>>(x, ln1_sg, ln1_sb, ln1_rg, ln1_rb, h);

    // 2) Fused QKV projection -> mid [NTOK, 3072]
    gemm_tc<false, false, false, false, false><<<dim3(24, 33, 1), 256, GEMM_SMEM>>>(
        h, wr + WR_WQ, mid, NTOK, QKV_STR, EMBED, nullptr, nullptr, 0, 0, 0,
        nullptr, nullptr, nullptr, nullptr, nullptr);

    // 3) Sparse masked attention (tensor-core reg path)
    attn_reg_kernel<<<dim3(NCHUNK, HEADS, BSZ), 256, ATTN_SMEM>>>(mid, ranges, ctx);
    attn_sum_kernel<<<(BSZ * HEADS * SUM_LEN) / 8, 256>>>(mid, ranges, ctx);

    // 4) Output projection + residual: x1 = x + ctx @ Wo^T
    gemm_tc<false, false, true, false, false><<<dim3(8, 33, 1), 256, GEMM_SMEM>>>(
        ctx, wr + WR_WO, x1, NTOK, EMBED, EMBED, nullptr, x, 0, 0, 0,
        nullptr, nullptr, nullptr, nullptr, nullptr);

    // 5) LN2
    ln_kernel<<<NTOK, 256>>>(x1, ln2_sg, ln2_sb, ln2_rg, ln2_rb, h2);

    // 6) FFN — reg segments with folded sum block (y = 16)
    gemm_tc<true, true, false, true, true><<<dim3(32, 17, BSZ), 256, GEMM_SMEM>>>(
        h2 + (size_t)SUM_LEN * EMBED, wr + WR_RFC1, mid + (size_t)SUM_LEN * FFN_DIM,
        REG_LEN, FFN_DIM, EMBED, rfc1b, nullptr, zE, zF, 0,
        h2, wr + WR_SFC1, sfc1b, nullptr, mid);
    gemm_tc<false, true, true, false, true><<<dim3(8, 17, BSZ), 256, GEMM_SMEM>>>(
        mid + (size_t)SUM_LEN * FFN_DIM, wr + WR_RFC2, out + (size_t)SUM_LEN * EMBED,
        REG_LEN, EMBED, FFN_DIM, rfc2b, x1 + (size_t)SUM_LEN * EMBED, zF, zE, zE,
        mid, wr + WR_SFC2, sfc2b, x1, out);
}

// round 11
// speedup vs baseline: 5.5732x; 1.0711x over previous
#include <cuda_runtime.h>
#include <cstdint>
#include <cstddef>

// ---------------------------------------------------------------------------
#define EMBED    1024
#define HEADS    16
#define HEAD_DIM 64
#define FFN_DIM  4096
#define BSZ      2
#define SUM_LEN  16
#define REG_LEN  2048
#define TOTAL    (SUM_LEN + REG_LEN)   // 2064
#define NCHUNK   16
#define NTOK     (BSZ * TOTAL)         // 4128
#define QKV_STR  3072                  // fused qkv row stride

// tensor-core attention tile constants
#define PADK   144
#define VSTR   148
#define QS_OFF 0
#define KS_OFF 8192
#define VT_OFF 17408
#define ATTN_SMEM ((VT_OFF + 64 * VSTR) * 4)   // 107,520 bytes

// ---------------------------------------------------------------------------
// Static device scratch (no cudaMalloc allowed)
// ---------------------------------------------------------------------------
__device__ __align__(1024) float g_h  [(size_t)NTOK * EMBED];
__device__ __align__(1024) float g_ctx[(size_t)NTOK * EMBED];
__device__ __align__(1024) float g_x1 [(size_t)NTOK * EMBED];
__device__ __align__(1024) float g_h2 [(size_t)NTOK * EMBED];
__device__ __align__(1024) float g_mid[(size_t)NTOK * FFN_DIM];  // qkv, then ffn mid
// tf32-rounded fused qkv weight only: [wq;wk;wv] contiguous (3M floats)
__device__ __align__(1024) float g_wr[(size_t)3 * 1024 * 1024];

// ---------------------------------------------------------------------------
// PTX helpers
// ---------------------------------------------------------------------------
__device__ __forceinline__ uint32_t smem_u32(const void* p) {
    uint32_t a;
    asm("{ .reg .u64 t; cvta.to.shared.u64 t, %1; cvt.u32.u64 %0, t; }"
        : "=r"(a) : "l"(p));
    return a;
}
__device__ __forceinline__ float f2tf32(float f) {
    unsigned u;
    asm("cvt.rna.tf32.f32 %0, %1;" : "=r"(u) : "f"(f));
    return __uint_as_float(u);
}
__device__ __forceinline__ float4 cvt4(float4 v) {
    return make_float4(f2tf32(v.x), f2tf32(v.y), f2tf32(v.z), f2tf32(v.w));
}
__device__ __forceinline__ void mma_tf32(float* d, const unsigned* a, const unsigned* b) {
    asm volatile(
        "mma.sync.aligned.m16n8k8.row.col.f32.tf32.tf32.f32 "
        "{%0,%1,%2,%3}, {%4,%5,%6,%7}, {%8,%9}, {%0,%1,%2,%3};"
        : "+f"(d[0]), "+f"(d[1]), "+f"(d[2]), "+f"(d[3])
        : "r"(a[0]), "r"(a[1]), "r"(a[2]), "r"(a[3]), "r"(b[0]), "r"(b[1]));
}
__device__ __forceinline__ void ldsm_x4(unsigned* r, uint32_t addr) {
    asm volatile("ldmatrix.sync.aligned.m8n8.x4.shared.b16 {%0,%1,%2,%3}, [%4];"
                 : "=r"(r[0]), "=r"(r[1]), "=r"(r[2]), "=r"(r[3]) : "r"(addr));
}
#define CP_ASYNC16(dst, src, sz) \
    asm volatile("cp.async.cg.shared.global [%0], [%1], 16, %2;" \
                 :: "r"(dst), "l"(src), "r"(sz) : "memory")
#define CP_COMMIT() asm volatile("cp.async.commit_group;" ::: "memory")
#define CP_WAIT2()  asm volatile("cp.async.wait_group 2;" ::: "memory")
#define CP_WAIT0()  asm volatile("cp.async.wait_group 0;" ::: "memory")

// ---------------------------------------------------------------------------
// TF32 tensor-core GEMM (NT), optional folded second problem on last y-block.
// 128x128 tile, BK=16, 256 threads (8 warps 4x2), cp.async 4-stage, 1 sync/iter.
// B operand may be raw f32 (mma truncates to tf32).
// ---------------------------------------------------------------------------
#define STAGES 4
#define STAGE_BYTES 16384
#define GEMM_SMEM (STAGES * STAGE_BYTES)

template<bool RELU, bool HAS_BIAS, bool HAS_RESID, bool ROUND_OUT, bool FOLD>
__global__ __launch_bounds__(256) void gemm_tc(
    const float* __restrict__ A, const float* __restrict__ B,
    float* __restrict__ C, int M, int NC, int K,
    const float* __restrict__ bias, const float* __restrict__ resid,
    size_t zA, size_t zC, size_t zR,
    const float* A2, const float* B2, const float* bias2,
    const float* resid2, float* C2)
{
    extern __shared__ char smraw[];
    const uint32_t smb = smem_u32(smraw);

    const bool sumblk = FOLD && (blockIdx.y == gridDim.y - 1);
    if (sumblk) { A = A2; B = B2; bias = bias2; resid = resid2; C = C2; M = SUM_LEN; }
    const int by = sumblk ? 0 : blockIdx.y;

    A += (size_t)blockIdx.z * zA;
    C += (size_t)blockIdx.z * zC;
    if (HAS_RESID) resid += (size_t)blockIdx.z * zR;

    const int tid  = threadIdx.x;
    const int lane = tid & 31;
    const int warp = tid >> 5;
    const int wm   = (warp >> 1) * 32;
    const int wn   = (warp & 1) * 64;

    const int srow = tid >> 1;
    const int scol = (tid & 1) * 2;
    const int rowA = by * 128 + srow;
    const int rowB = blockIdx.x * 128 + srow;
    const uint32_t asz = (rowA < M) ? 16u : 0u;
    const float* Ag = A + (size_t)(rowA < M ? rowA : 0) * K + scol * 4;
    const float* Bg = B + (size_t)rowB * K + scol * 4;
    const uint32_t ssw  = (srow >> 1) & 3;
    const uint32_t dst0 = srow * 64 + (((uint32_t)scol ^ ssw) << 4);
    const uint32_t dst1 = srow * 64 + ((((uint32_t)scol + 1) ^ ssw) << 4);

    const int arow0 = wm + (lane & 15);
    const uint32_t aoff0 = arow0 * 64,        ask0 = (arow0 >> 1) & 3;
    const uint32_t aoff1 = (arow0 + 16) * 64, ask1 = ((arow0 + 16) >> 1) & 3;
    const uint32_t acb = lane >> 4;
    const int bn = wn + ((lane >> 4) << 3) + (lane & 7);
    const uint32_t bcb = (lane >> 3) & 1;
    uint32_t boff[4], bsk[4];
#pragma unroll
    for (int p = 0; p < 4; p++) {
        int n = bn + p * 16;
        boff[p] = n * 64;
        bsk[p]  = (n >> 1) & 3;
    }

    float acc[2][8][4];
#pragma unroll
    for (int mt = 0; mt < 2; mt++)
#pragma unroll
        for (int nt = 0; nt < 8; nt++)
#pragma unroll
            for (int i = 0; i < 4; i++) acc[mt][nt][i] = 0.f;

    const int nstep = K >> 4;

#pragma unroll
    for (int s = 0; s < STAGES - 1; s++) {
        uint32_t ab = smb + s * STAGE_BYTES;
        uint32_t bb = ab + 8192;
        const float* ag = Ag + s * 16;
        const float* bg = Bg + s * 16;
        CP_ASYNC16(ab + dst0, ag,     asz);
        CP_ASYNC16(ab + dst1, ag + 4, asz);
        CP_ASYNC16(bb + dst0, bg,     16u);
        CP_ASYNC16(bb + dst1, bg + 4, 16u);
        CP_COMMIT();
    }

    for (int i = 0; i < nstep; i++) {
        CP_WAIT2();
        __syncthreads();

        const int nf = i + STAGES - 1;
        if (nf < nstep) {
            uint32_t ab = smb + (nf % STAGES) * STAGE_BYTES;
            uint32_t bb = ab + 8192;
            const float* ag = Ag + nf * 16;
            const float* bg = Bg + nf * 16;
            CP_ASYNC16(ab + dst0, ag,     asz);
            CP_ASYNC16(ab + dst1, ag + 4, asz);
            CP_ASYNC16(bb + dst0, bg,     16u);
            CP_ASYNC16(bb + dst1, bg + 4, 16u);
        }
        CP_COMMIT();

        const uint32_t ab = smb + (i % STAGES) * STAGE_BYTES;
        const uint32_t bb = ab + 8192;

#pragma unroll
        for (int sub = 0; sub < 2; sub++) {
            const uint32_t ch = sub * 2 + acb;
            unsigned a0[4], a1[4], b[4][4];
            ldsm_x4(a0, ab + aoff0 + ((ch ^ ask0) << 4));
            ldsm_x4(a1, ab + aoff1 + ((ch ^ ask1) << 4));
            const uint32_t chb = sub * 2 + bcb;
#pragma unroll
            for (int p = 0; p < 4; p++)
                ldsm_x4(b[p], bb + boff[p] + ((chb ^ bsk[p]) << 4));
#pragma unroll
            for (int p = 0; p < 4; p++) {
                mma_tf32(acc[0][2 * p    ], a0, &b[p][0]);
                mma_tf32(acc[0][2 * p + 1], a0, &b[p][2]);
                mma_tf32(acc[1][2 * p    ], a1, &b[p][0]);
                mma_tf32(acc[1][2 * p + 1], a1, &b[p][2]);
            }
        }
    }

    const int fr = lane >> 2, fk = lane & 3;
    const int rowbase = by * 128 + wm + fr;
    const int colbase = blockIdx.x * 128 + wn + fk * 2;
#pragma unroll
    for (int mt = 0; mt < 2; mt++) {
#pragma unroll
        for (int half = 0; half < 2; half++) {
            int r = rowbase + mt * 16 + half * 8;
            if (r >= M) continue;
#pragma unroll
            for (int nt = 0; nt < 8; nt++) {
                int cidx = colbase + nt * 8;
                float v0 = acc[mt][nt][half * 2 + 0];
                float v1 = acc[mt][nt][half * 2 + 1];
                if (HAS_BIAS) { v0 += bias[cidx]; v1 += bias[cidx + 1]; }
                if (RELU) { v0 = fmaxf(v0, 0.f); v1 = fmaxf(v1, 0.f); }
                if (HAS_RESID) {
                    float2 rr = *(const float2*)(resid + (size_t)r * NC + cidx);
                    v0 += rr.x; v1 += rr.y;
                }
                if (ROUND_OUT) { v0 = f2tf32(v0); v1 = f2tf32(v1); }
                *(float2*)(C + (size_t)r * NC + cidx) = make_float2(v0, v1);
            }
        }
    }
}

// ---------------------------------------------------------------------------
// Round only the fused QKV weight concat (wq|wk|wv) to tf32-rna
// ---------------------------------------------------------------------------
struct RoundSrcs3 { const float4* s[3]; };

__global__ __launch_bounds__(256) void round_qkv_kernel(
    RoundSrcs3 srcs, float4* __restrict__ dst)
{
    size_t i = (size_t)blockIdx.x * 256 + threadIdx.x;   // < 786432
    int r = (int)(i >> 18);
    dst[i] = cvt4(srcs.s[r][i - ((size_t)r << 18)]);
}

// ---------------------------------------------------------------------------
// LayerNorm (output rounded to tf32)
// ---------------------------------------------------------------------------
__global__ __launch_bounds__(256) void ln_kernel(
    const float* __restrict__ x,
    const float* __restrict__ gs, const float* __restrict__ bs,
    const float* __restrict__ gr, const float* __restrict__ br,
    float* __restrict__ out)
{
    int row = blockIdx.x;
    int t = row % TOTAL;
    const float* g = (t < SUM_LEN) ? gs : gr;
    const float* b = (t < SUM_LEN) ? bs : br;
    int tid = threadIdx.x;
    int lane = tid & 31, warp = tid >> 5;

    float4 v = ((const float4*)(x + (size_t)row * EMBED))[tid];
    float s = v.x + v.y + v.z + v.w;
    float q = v.x * v.x + v.y * v.y + v.z * v.z + v.w * v.w;

    __shared__ float rs_[8], rq_[8];
#pragma unroll
    for (int o = 16; o; o >>= 1) {
        s += __shfl_xor_sync(0xffffffffu, s, o);
        q += __shfl_xor_sync(0xffffffffu, q, o);
    }
    if (lane == 0) { rs_[warp] = s; rq_[warp] = q; }
    __syncthreads();
    if (tid < 32) {
        s = (lane < 8) ? rs_[lane] : 0.f;
        q = (lane < 8) ? rq_[lane] : 0.f;
#pragma unroll
        for (int o = 4; o; o >>= 1) {
            s += __shfl_xor_sync(0xffffffffu, s, o);
            q += __shfl_xor_sync(0xffffffffu, q, o);
        }
        if (lane == 0) { rs_[0] = s; rq_[0] = q; }
    }
    __syncthreads();

    float mean = rs_[0] * (1.f / EMBED);
    float var  = rq_[0] * (1.f / EMBED) - mean * mean;
    float rinv = rsqrtf(var + 1e-5f);

    float4 gg = ((const float4*)g)[tid];
    float4 bb = ((const float4*)b)[tid];
    float4 o4;
    o4.x = (v.x - mean) * rinv * gg.x + bb.x;
    o4.y = (v.y - mean) * rinv * gg.y + bb.y;
    o4.z = (v.z - mean) * rinv * gg.z + bb.z;
    o4.w = (v.w - mean) * rinv * gg.w + bb.w;
    ((float4*)(out + (size_t)row * EMBED))[tid] = cvt4(o4);
}

// ---------------------------------------------------------------------------
// TENSOR-CORE attention for REG queries. Grid (NCHUNK, HEADS, BSZ), 256 thr.
// Q/K staged RAW via cp.async (MMA truncates); scale 0.125 applied post-MMA.
// V transposed via LDG+STS (overlaps the cp.async groups).
// ---------------------------------------------------------------------------
__global__ __launch_bounds__(256) void attn_reg_kernel(
    const float* __restrict__ QKV, const int* __restrict__ ranges,
    float* __restrict__ CTX)
{
    extern __shared__ float sm[];
    const uint32_t smb = smem_u32(sm);
    const uint32_t QS = smb + QS_OFF * 4;
    const uint32_t KS = smb + KS_OFF * 4;
    const uint32_t VT = smb + VT_OFF * 4;

    const int c = blockIdx.x, h = blockIdx.y, b = blockIdx.z;
    const int start = ranges[(b * NCHUNK + c) * 2];
    const int next  = (c + 1 < NCHUNK) ? ranges[(b * NCHUNK + c + 1) * 2] : REG_LEN;
    const int width = next - start;
    const int nsum  = c;
    const int nk    = nsum + width;
    const size_t bb = (size_t)b * TOTAL;

    const int tid = threadIdx.x;

    // ---- stage Q raw via cp.async, swizzled 16B chunks ----
    for (int idx = tid; idx < 128 * 16; idx += 256) {
        int row = idx >> 4, ch = idx & 15;
        int tok = SUM_LEN + start + row;
        const float* src = QKV + (bb + tok) * QKV_STR + h * HEAD_DIM + ch * 4;
        CP_ASYNC16(QS + row * 256 + (((uint32_t)ch ^ (uint32_t)(row & 15)) << 4),
                   src, 16u);
    }
    // ---- stage K raw via cp.async (zero-fill padded rows via src-size=0) ----
    for (int idx = tid; idx < PADK * 16; idx += 256) {
        int j = idx >> 4, ch = idx & 15;
        uint32_t sz = (j < nk) ? 16u : 0u;
        int tok = (j < nsum) ? j : (j < nk ? SUM_LEN + start + (j - nsum) : 0);
        const float* src = QKV + (bb + tok) * QKV_STR + h * HEAD_DIM + 1024 + ch * 4;
        CP_ASYNC16(KS + j * 256 + (((uint32_t)ch ^ (uint32_t)(j & 15)) << 4),
                   src, sz);
    }
    CP_COMMIT();

    // ---- stage V transposed (LDG overlaps cp.async groups) ----
    for (int idx = tid; idx < PADK * 16; idx += 256) {
        int j = idx >> 4, ch = idx & 15;
        float4 t4 = make_float4(0.f, 0.f, 0.f, 0.f);
        if (j < nk) {
            int tok = (j < nsum) ? j : (SUM_LEN + start + (j - nsum));
            t4 = *(const float4*)(QKV + (bb + tok) * QKV_STR + h * HEAD_DIM
                                  + 2048 + ch * 4);
        }
        int d = ch * 4;
        sm[VT_OFF + (d + 0) * VSTR + j] = t4.x;
        sm[VT_OFF + (d + 1) * VSTR + j] = t4.y;
        sm[VT_OFF + (d + 2) * VSTR + j] = t4.z;
        sm[VT_OFF + (d + 3) * VSTR + j] = t4.w;
    }
    CP_WAIT0();
    __syncthreads();

    const int lane = tid & 31, wid = tid >> 5;
    const int fr = lane >> 2, fk = lane & 3;

    // ---- phase 1: S[128,144] = Q @ K^T (raw; scaled after) ----
    float S[18][4];
#pragma unroll
    for (int t = 0; t < 18; t++)
#pragma unroll
        for (int i = 0; i < 4; i++) S[t][i] = 0.f;

    {
        const int arow = wid * 16 + (lane & 15);
        const uint32_t abase = QS + (arow * 64) * 4;
        const uint32_t asw   = (arow & 15);
        const int krow = ((lane >> 4) << 3) + (lane & 7);
        const uint32_t kcb = (lane >> 3) & 1;
#pragma unroll
        for (int k8 = 0; k8 < 8; k8++) {
            unsigned a[4];
            uint32_t ach = 2 * k8 + (lane >> 4);
            ldsm_x4(a, abase + ((ach ^ asw) << 4));
            uint32_t bch = 2 * k8 + kcb;
#pragma unroll
            for (int p = 0; p < 9; p++) {
                unsigned bf[4];
                int kr = 16 * p + krow;
                ldsm_x4(bf, KS + (kr * 64) * 4 + ((bch ^ (uint32_t)(kr & 15)) << 4));
                mma_tf32(S[2 * p],     a, &bf[0]);
                mma_tf32(S[2 * p + 1], a, &bf[2]);
            }
        }
    }

    // ---- scale + mask + softmax ----
    const int q0 = wid * 16 + fr;
    const int lim0 = nsum + q0, lim1 = lim0 + 8;
    float m0 = -1e30f, m1 = -1e30f;
#pragma unroll
    for (int t = 0; t < 18; t++) {
        int cb = 8 * t + 2 * fk;
        S[t][0] = (cb     <= lim0) ? S[t][0] * 0.125f : -1e30f;
        S[t][1] = (cb + 1 <= lim0) ? S[t][1] * 0.125f : -1e30f;
        S[t][2] = (cb     <= lim1) ? S[t][2] * 0.125f : -1e30f;
        S[t][3] = (cb + 1 <= lim1) ? S[t][3] * 0.125f : -1e30f;
        m0 = fmaxf(m0, fmaxf(S[t][0], S[t][1]));
        m1 = fmaxf(m1, fmaxf(S[t][2], S[t][3]));
    }
    m0 = fmaxf(m0, __shfl_xor_sync(0xffffffffu, m0, 1));
    m0 = fmaxf(m0, __shfl_xor_sync(0xffffffffu, m0, 2));
    m1 = fmaxf(m1, __shfl_xor_sync(0xffffffffu, m1, 1));
    m1 = fmaxf(m1, __shfl_xor_sync(0xffffffffu, m1, 2));

    float l0 = 0.f, l1 = 0.f;
#pragma unroll
    for (int t = 0; t < 18; t++) {
        S[t][0] = f2tf32(__expf(S[t][0] - m0));
        S[t][1] = f2tf32(__expf(S[t][1] - m0));
        S[t][2] = f2tf32(__expf(S[t][2] - m1));
        S[t][3] = f2tf32(__expf(S[t][3] - m1));
        l0 += S[t][0] + S[t][1];
        l1 += S[t][2] + S[t][3];
    }
    l0 += __shfl_xor_sync(0xffffffffu, l0, 1);
    l0 += __shfl_xor_sync(0xffffffffu, l0, 2);
    l1 += __shfl_xor_sync(0xffffffffu, l1, 1);
    l1 += __shfl_xor_sync(0xffffffffu, l1, 2);

    // ---- phase 2: O = P @ V (C-frag -> A-frag via shfl) ----
    float O[8][4];
#pragma unroll
    for (int nt = 0; nt < 8; nt++)
#pragma unroll
        for (int i = 0; i < 4; i++) O[nt][i] = 0.f;

    const int s0 = (lane & ~3) | (fk >> 1);
    const int s1 = s0 + 2;
    const bool e = fk & 1;
    const int vrow0 = ((lane >> 4) << 3) + (lane & 7);
    const uint32_t vcb = (lane >> 3) & 1;

#pragma unroll
    for (int t = 0; t < 18; t++) {
        float x0 = __shfl_sync(0xffffffffu, S[t][0], s0);
        float x1 = __shfl_sync(0xffffffffu, S[t][1], s0);
        float x2 = __shfl_sync(0xffffffffu, S[t][2], s0);
        float x3 = __shfl_sync(0xffffffffu, S[t][3], s0);
        float y0 = __shfl_sync(0xffffffffu, S[t][0], s1);
        float y1 = __shfl_sync(0xffffffffu, S[t][1], s1);
        float y2 = __shfl_sync(0xffffffffu, S[t][2], s1);
        float y3 = __shfl_sync(0xffffffffu, S[t][3], s1);
        unsigned a[4];
        a[0] = __float_as_uint(e ? x1 : x0);
        a[1] = __float_as_uint(e ? x3 : x2);
        a[2] = __float_as_uint(e ? y1 : y0);
        a[3] = __float_as_uint(e ? y3 : y2);
        const uint32_t vch = (2 * t + vcb) << 4;
#pragma unroll
        for (int pn = 0; pn < 4; pn++) {
            unsigned bf[4];
            int vr = 16 * pn + vrow0;
            ldsm_x4(bf, VT + (vr * VSTR) * 4 + vch);
            mma_tf32(O[2 * pn],     a, &bf[0]);
            mma_tf32(O[2 * pn + 1], a, &bf[2]);
        }
    }

    // ---- normalize + store ----
    const float inv0 = 1.f / l0, inv1 = 1.f / l1;
    if (q0 < width) {
        int tok = SUM_LEN + start + q0;
        float* op = CTX + (bb + tok) * EMBED + h * HEAD_DIM + 2 * fk;
#pragma unroll
        for (int nt = 0; nt < 8; nt++)
            *(float2*)(op + 8 * nt) =
                make_float2(f2tf32(O[nt][0] * inv0), f2tf32(O[nt][1] * inv0));
    }
    if (q0 + 8 < width) {
        int tok = SUM_LEN + start + q0 + 8;
        float* op = CTX + (bb + tok) * EMBED + h * HEAD_DIM + 2 * fk;
#pragma unroll
        for (int nt = 0; nt < 8; nt++)
            *(float2*)(op + 8 * nt) =
                make_float2(f2tf32(O[nt][2] * inv1), f2tf32(O[nt][3] * inv1));
    }
}

// ---------------------------------------------------------------------------
// Attention, SUM queries. One warp per (b, h, s); qkv fused buffer.
// ---------------------------------------------------------------------------
__global__ __launch_bounds__(256) void attn_sum_kernel(
    const float* __restrict__ QKV, const int* __restrict__ ranges,
    float* __restrict__ CTX)
{
    int gw = (blockIdx.x * blockDim.x + threadIdx.x) >> 5;
    int lane = threadIdx.x & 31;
    if (gw >= BSZ * HEADS * SUM_LEN) return;
    int b = gw / (HEADS * SUM_LEN);
    int rem = gw % (HEADS * SUM_LEN);
    int h = rem / SUM_LEN;
    int s = rem % SUM_LEN;

    int start = ranges[(b * NCHUNK + s) * 2];
    int next  = (s + 1 < NCHUNK) ? ranges[(b * NCHUNK + s + 1) * 2] : REG_LEN;

    size_t bbase = (size_t)b * TOTAL;
    float2 q2 = ((const float2*)(QKV + (bbase + s) * QKV_STR + h * HEAD_DIM))[lane];
    q2.x *= 0.125f; q2.y *= 0.125f;

    float m = -1e30f, l = 0.f, cx = 0.f, cy = 0.f;

#define ASTEP(tok_expr)                                                                 \
    do {                                                                                \
        int tok = (tok_expr);                                                           \
        size_t ko = (bbase + tok) * QKV_STR + h * HEAD_DIM;                             \
        float2 kk = ((const float2*)(QKV + ko + 1024))[lane];                           \
        float part = q2.x * kk.x + q2.y * kk.y;                                         \
        _Pragma("unroll")                                                               \
        for (int o = 16; o; o >>= 1) part += __shfl_xor_sync(0xffffffffu, part, o);     \
        float mn = fmaxf(m, part);                                                      \
        float alpha = __expf(m - mn);                                                   \
        float p = __expf(part - mn);                                                    \
        l = l * alpha + p;                                                              \
        float2 vv = ((const float2*)(QKV + ko + 2048))[lane];                           \
        cx = fmaf(p, vv.x, cx * alpha);                                                 \
        cy = fmaf(p, vv.y, cy * alpha);                                                 \
        m = mn;                                                                         \
    } while (0)

    for (int t = 0; t <= s; t++)       ASTEP(t);
    for (int t = start; t < next; t++) ASTEP(SUM_LEN + t);
#undef ASTEP

    float inv = 1.f / l;
    ((float2*)(CTX + (bbase + s) * EMBED + h * HEAD_DIM))[lane] =
        make_float2(f2tf32(cx * inv), f2tf32(cy * inv));
}

// ---------------------------------------------------------------------------
// Launch sequence
// ---------------------------------------------------------------------------
extern "C" void kernel_launch(void* const* d_in, const int* in_sizes, int n_in,
                              void* d_out, int out_size)
{
    const float* x      = (const float*)d_in[0];
    const float* w_q    = (const float*)d_in[1];
    const float* w_k    = (const float*)d_in[2];
    const float* w_v    = (const float*)d_in[3];
    const float* w_o    = (const float*)d_in[4];
    const float* ln1_sg = (const float*)d_in[5];
    const float* ln1_sb = (const float*)d_in[6];
    const float* ln1_rg = (const float*)d_in[7];
    const float* ln1_rb = (const float*)d_in[8];
    const float* sfc1w  = (const float*)d_in[9];
    const float* sfc1b  = (const float*)d_in[10];
    const float* sfc2w  = (const float*)d_in[11];
    const float* sfc2b  = (const float*)d_in[12];
    const float* rfc1w  = (const float*)d_in[13];
    const float* rfc1b  = (const float*)d_in[14];
    const float* rfc2w  = (const float*)d_in[15];
    const float* rfc2b  = (const float*)d_in[16];
    const float* ln2_sg = (const float*)d_in[17];
    const float* ln2_sb = (const float*)d_in[18];
    const float* ln2_rg = (const float*)d_in[19];
    const float* ln2_rb = (const float*)d_in[20];
    const int*   ranges = (const int*)d_in[21];
    float* out = (float*)d_out;

    void *ph, *pctx, *px1, *ph2, *pmid, *pwr;
    cudaGetSymbolAddress(&ph,   g_h);
    cudaGetSymbolAddress(&pctx, g_ctx);
    cudaGetSymbolAddress(&px1,  g_x1);
    cudaGetSymbolAddress(&ph2,  g_h2);
    cudaGetSymbolAddress(&pmid, g_mid);
    cudaGetSymbolAddress(&pwr,  g_wr);
    float* h   = (float*)ph;
    float* ctx = (float*)pctx;
    float* x1  = (float*)px1;
    float* h2  = (float*)ph2;
    float* mid = (float*)pmid;
    float* wr  = (float*)pwr;

    const size_t zE = (size_t)TOTAL * EMBED;
    const size_t zF = (size_t)TOTAL * FFN_DIM;

    cudaFuncSetAttribute(attn_reg_kernel,
                         cudaFuncAttributeMaxDynamicSharedMemorySize, ATTN_SMEM);
    cudaFuncSetAttribute(attn_reg_kernel,
                         cudaFuncAttributePreferredSharedMemoryCarveout, 100);
    cudaFuncSetAttribute(gemm_tc<false, false, false, false, false>,
                         cudaFuncAttributeMaxDynamicSharedMemorySize, GEMM_SMEM);
    cudaFuncSetAttribute(gemm_tc<false, false, false, false, false>,
                         cudaFuncAttributePreferredSharedMemoryCarveout, 100);
    cudaFuncSetAttribute(gemm_tc<false, false, true, false, false>,
                         cudaFuncAttributeMaxDynamicSharedMemorySize, GEMM_SMEM);
    cudaFuncSetAttribute(gemm_tc<false, false, true, false, false>,
                         cudaFuncAttributePreferredSharedMemoryCarveout, 100);
    cudaFuncSetAttribute(gemm_tc<true, true, false, true, true>,
                         cudaFuncAttributeMaxDynamicSharedMemorySize, GEMM_SMEM);
    cudaFuncSetAttribute(gemm_tc<true, true, false, true, true>,
                         cudaFuncAttributePreferredSharedMemoryCarveout, 100);
    cudaFuncSetAttribute(gemm_tc<false, true, true, false, true>,
                         cudaFuncAttributeMaxDynamicSharedMemorySize, GEMM_SMEM);
    cudaFuncSetAttribute(gemm_tc<false, true, true, false, true>,
                         cudaFuncAttributePreferredSharedMemoryCarveout, 100);

    // 0) Round ONLY the fused qkv weight concat to tf32 (rna)
    {
        RoundSrcs3 rs;
        rs.s[0] = (const float4*)w_q;
        rs.s[1] = (const float4*)w_k;
        rs.s[2] = (const float4*)w_v;
        round_qkv_kernel<<<3072, 256>>>(rs, (float4*)wr);
    }

    // 1) LN1
    ln_kernel<<<NTOK, 256>>>(x, ln1_sg, ln1_sb, ln1_rg, ln1_rb, h);

    // 2) Fused QKV projection -> mid [NTOK, 3072]
    gemm_tc<false, false, false, false, false><<<dim3(24, 33, 1), 256, GEMM_SMEM>>>(
        h, wr, mid, NTOK, QKV_STR, EMBED, nullptr, nullptr, 0, 0, 0,
        nullptr, nullptr, nullptr, nullptr, nullptr);

    // 3) Sparse masked attention (tensor-core reg path)
    attn_reg_kernel<<<dim3(NCHUNK, HEADS, BSZ), 256, ATTN_SMEM>>>(mid, ranges, ctx);
    attn_sum_kernel<<<(BSZ * HEADS * SUM_LEN) / 8, 256>>>(mid, ranges, ctx);

    // 4) Output projection + residual: x1 = x + ctx @ Wo^T (raw w_o, MMA truncates)
    gemm_tc<false, false, true, false, false><<<dim3(8, 33, 1), 256, GEMM_SMEM>>>(
        ctx, w_o, x1, NTOK, EMBED, EMBED, nullptr, x, 0, 0, 0,
        nullptr, nullptr, nullptr, nullptr, nullptr);

    // 5) LN2
    ln_kernel<<<NTOK, 256>>>(x1, ln2_sg, ln2_sb, ln2_rg, ln2_rb, h2);

    // 6) FFN — reg segments with folded sum block (raw weights)
    gemm_tc<true, true, false, true, true><<<dim3(32, 17, BSZ), 256, GEMM_SMEM>>>(
        h2 + (size_t)SUM_LEN * EMBED, rfc1w, mid + (size_t)SUM_LEN * FFN_DIM,
        REG_LEN, FFN_DIM, EMBED, rfc1b, nullptr, zE, zF, 0,
        h2, sfc1w, sfc1b, nullptr, mid);
    gemm_tc<false, true, true, false, true><<<dim3(8, 17, BSZ), 256, GEMM_SMEM>>>(
        mid + (size_t)SUM_LEN * FFN_DIM, rfc2w, out + (size_t)SUM_LEN * EMBED,
        REG_LEN, EMBED, FFN_DIM, rfc2b, x1 + (size_t)SUM_LEN * EMBED, zF, zE, zE,
        mid, sfc2w, sfc2b, x1, out);
}